// round 1
// baseline (speedup 1.0000x reference)
#include <cuda_runtime.h>

// ---------------------------------------------------------------------------
// WindowAttention (Swin): qkv GEMM -> windowed attention -> proj GEMM
// fp32 throughout, using packed fma.rn.f32x2 (FFMA2) for 2x fp32 FMA rate.
// ---------------------------------------------------------------------------

#define DIM     384
#define NHEAD   12
#define HD      32
#define NTOK    49
#define BWIN    4096
#define NWMASK  64
#define M_ROWS  (BWIN * NTOK)        // 200704

// Scratch (static device arrays: allocation-guard safe)
__device__ float g_qkv[(size_t)M_ROWS * 3 * DIM];   // [200704, 1152]
__device__ float g_att[(size_t)M_ROWS * DIM];       // [200704, 384]

// ---------------- f32x2 helpers ----------------
__device__ __forceinline__ unsigned long long dup_f32(float x) {
    unsigned long long r;
    asm("mov.b64 %0, {%1, %1};" : "=l"(r) : "f"(x));
    return r;
}
__device__ __forceinline__ void ffma2(unsigned long long& c,
                                      unsigned long long a,
                                      unsigned long long b) {
    asm("fma.rn.f32x2 %0, %1, %2, %0;" : "+l"(c) : "l"(a), "l"(b));
}
__device__ __forceinline__ void unpack2(unsigned long long v, float& lo, float& hi) {
    asm("mov.b64 {%0, %1}, %2;" : "=f"(lo), "=f"(hi) : "l"(v));
}

// ---------------------------------------------------------------------------
// C[M,N] = A[M,K] * B[N,K]^T + bias[N]     (both operands K-contiguous, "NT")
// BM=BN=128, BK=16, 256 threads, 8x8 per thread via f32x2 packed FMA.
// Requires: M % 128 == 0, N % 128 == 0, K % 16 == 0.
// ---------------------------------------------------------------------------
__global__ __launch_bounds__(256, 2)
void sgemm_nt(const float* __restrict__ A, const float* __restrict__ Bm,
              const float* __restrict__ bias, float* __restrict__ C,
              int M, int N, int K)
{
    __shared__ float As[16][128];
    __shared__ float Bs[16][128];

    const int tid = threadIdx.x;
    const int tx = tid & 15;        // column group (8 cols)
    const int ty = tid >> 4;        // row group (8 rows)
    const int bm = blockIdx.y * 128;
    const int bn = blockIdx.x * 128;

    unsigned long long c2[8][4];
#pragma unroll
    for (int i = 0; i < 8; i++)
#pragma unroll
        for (int j = 0; j < 4; j++) c2[i][j] = 0ull;

    for (int kk = 0; kk < K; kk += 16) {
        // Load 128x16 tiles of A and B, store transposed [k][row]
#pragma unroll
        for (int l = 0; l < 2; l++) {
            int f   = tid + l * 256;      // 0..511 -> 128 rows x 4 float4
            int row = f >> 2;
            int c4  = (f & 3) * 4;
            float4 va = *(const float4*)(A  + (size_t)(bm + row) * K + kk + c4);
            As[c4 + 0][row] = va.x; As[c4 + 1][row] = va.y;
            As[c4 + 2][row] = va.z; As[c4 + 3][row] = va.w;
            float4 vb = *(const float4*)(Bm + (size_t)(bn + row) * K + kk + c4);
            Bs[c4 + 0][row] = vb.x; Bs[c4 + 1][row] = vb.y;
            Bs[c4 + 2][row] = vb.z; Bs[c4 + 3][row] = vb.w;
        }
        __syncthreads();

#pragma unroll
        for (int k = 0; k < 16; k++) {
            unsigned long long b2[4], a2[8];
#pragma unroll
            for (int j = 0; j < 4; j++)
                b2[j] = *(const unsigned long long*)&Bs[k][tx * 8 + j * 2];
#pragma unroll
            for (int i = 0; i < 8; i++)
                a2[i] = dup_f32(As[k][ty * 8 + i]);
#pragma unroll
            for (int i = 0; i < 8; i++)
#pragma unroll
                for (int j = 0; j < 4; j++)
                    ffma2(c2[i][j], a2[i], b2[j]);
        }
        __syncthreads();
    }

    // Epilogue: add bias, store
#pragma unroll
    for (int i = 0; i < 8; i++) {
        int m = bm + ty * 8 + i;
        float* crow = C + (size_t)m * N + bn + tx * 8;
#pragma unroll
        for (int j = 0; j < 4; j++) {
            float lo, hi;
            unpack2(c2[i][j], lo, hi);
            int n = bn + tx * 8 + j * 2;
            float2 o;
            o.x = lo + bias[n];
            o.y = hi + bias[n + 1];
            *(float2*)(crow + j * 2) = o;
        }
    }
}

// ---------------------------------------------------------------------------
// Windowed attention: one block per (head, window).
// q,k,v are slices of g_qkv [200704, 1152]: q at col h*32, k at 384+h*32,
// v at 768+h*32. Output layout [m, h*32+d] (token-major, channel h*hd+d).
// ---------------------------------------------------------------------------
__global__ __launch_bounds__(256)
void attn_kernel(const float* __restrict__ qkv, const float* __restrict__ mask,
                 const float* __restrict__ bias_table, const int* __restrict__ rel_idx,
                 float* __restrict__ out)
{
    const int h = blockIdx.x;      // 0..11
    const int w = blockIdx.y;      // 0..4095
    const int tid = threadIdx.x;

    __shared__ __align__(16) float q[49][32];
    __shared__ __align__(16) float k[49][32];
    __shared__ __align__(16) float v[49][34];   // padded, 8B-aligned rows
    __shared__ float s[49][50];

    const size_t rowbase = (size_t)w * 49 * 1152 + h * 32;
    for (int t = tid; t < 49 * 32; t += 256) {
        int i = t >> 5, d = t & 31;
        const float* p = qkv + rowbase + (size_t)i * 1152 + d;
        q[i][d] = p[0];
        k[i][d] = p[384];
        v[i][d] = p[768];
    }
    __syncthreads();

    const float scale = 0.17677669529663687f;   // 32^-0.5
    const float* mrow = mask + (size_t)(w & 63) * 49 * 49;

    // scores: s[i][j] = scale * <q_i, k_j> + bias[h,i,j] + mask[w%64,i,j]
    for (int e = tid; e < 49 * 49; e += 256) {
        int i = e / 49, j = e - i * 49;
        unsigned long long acc = 0ull;
        const unsigned long long* q2 = (const unsigned long long*)q[i];
        const unsigned long long* k2 = (const unsigned long long*)k[j];
#pragma unroll
        for (int d2 = 0; d2 < 16; d2++) ffma2(acc, q2[d2], k2[d2]);
        float lo, hi;
        unpack2(acc, lo, hi);
        float b = bias_table[rel_idx[e] * NHEAD + h];
        s[i][j] = (lo + hi) * scale + b + mrow[e];
    }
    __syncthreads();

    // row softmax (one warp per row, rows strided by 8)
    const int warp = tid >> 5, lane = tid & 31;
    for (int r = warp; r < 49; r += 8) {
        float x0 = (lane < 49) ? s[r][lane] : -1e30f;
        float x1 = (lane + 32 < 49) ? s[r][lane + 32] : -1e30f;
        float mx = fmaxf(x0, x1);
#pragma unroll
        for (int o = 16; o > 0; o >>= 1)
            mx = fmaxf(mx, __shfl_xor_sync(0xffffffffu, mx, o));
        float e0 = (lane < 49) ? __expf(x0 - mx) : 0.f;
        float e1 = (lane + 32 < 49) ? __expf(x1 - mx) : 0.f;
        float sum = e0 + e1;
#pragma unroll
        for (int o = 16; o > 0; o >>= 1)
            sum += __shfl_xor_sync(0xffffffffu, sum, o);
        float inv = 1.0f / sum;
        if (lane < 49)      s[r][lane]      = e0 * inv;
        if (lane + 32 < 49) s[r][lane + 32] = e1 * inv;
    }
    __syncthreads();

    // out[i, d] = sum_j p[i][j] * v[j][d], packed over d pairs
    for (int e = tid; e < 49 * 16; e += 256) {
        int i = e >> 4, d2 = e & 15;
        unsigned long long acc = 0ull;
#pragma unroll
        for (int j = 0; j < 49; j++) {
            unsigned long long vv = *(const unsigned long long*)&v[j][2 * d2];
            ffma2(acc, dup_f32(s[i][j]), vv);
        }
        float lo, hi;
        unpack2(acc, lo, hi);
        float* op = out + ((size_t)w * 49 + i) * DIM + h * 32 + 2 * d2;
        op[0] = lo;
        op[1] = hi;
    }
}

// ---------------------------------------------------------------------------
extern "C" void kernel_launch(void* const* d_in, const int* in_sizes, int n_in,
                              void* d_out, int out_size)
{
    const float* x          = (const float*)d_in[0];
    const float* mask       = (const float*)d_in[1];
    const float* qkv_w      = (const float*)d_in[2];
    const float* qkv_b      = (const float*)d_in[3];
    const float* proj_w     = (const float*)d_in[4];
    const float* proj_b     = (const float*)d_in[5];
    const float* bias_table = (const float*)d_in[6];
    const int*   rel_idx    = (const int*)d_in[7];
    float* out = (float*)d_out;

    float* qkv_ptr = nullptr;
    float* att_ptr = nullptr;
    cudaGetSymbolAddress((void**)&qkv_ptr, g_qkv);
    cudaGetSymbolAddress((void**)&att_ptr, g_att);

    // 1) qkv = x @ qkv_w^T + qkv_b : [200704, 1152]
    {
        dim3 grid(3 * DIM / 128, M_ROWS / 128);   // 9 x 1568
        sgemm_nt<<<grid, 256>>>(x, qkv_w, qkv_b, qkv_ptr, M_ROWS, 3 * DIM, DIM);
    }
    // 2) attention per (head, window) -> g_att [200704, 384]
    {
        dim3 grid(NHEAD, BWIN);                   // 12 x 4096
        attn_kernel<<<grid, 256>>>(qkv_ptr, mask, bias_table, rel_idx, att_ptr);
    }
    // 3) out = g_att @ proj_w^T + proj_b : [200704, 384]
    {
        dim3 grid(DIM / 128, M_ROWS / 128);       // 3 x 1568
        sgemm_nt<<<grid, 256>>>(att_ptr, proj_w, proj_b, out, M_ROWS, DIM, DIM);
    }
}

// round 2
// speedup vs baseline: 1.0005x; 1.0005x over previous
#include <cuda_runtime.h>

// ---------------------------------------------------------------------------
// WindowAttention (Swin): qkv GEMM -> windowed attention -> proj GEMM
// fp32 throughout, using packed fma.rn.f32x2 (FFMA2) for 2x fp32 FMA rate.
// ---------------------------------------------------------------------------

#define DIM     384
#define NHEAD   12
#define HD      32
#define NTOK    49
#define BWIN    4096
#define NWMASK  64
#define M_ROWS  (BWIN * NTOK)        // 200704

// Scratch (static device arrays: allocation-guard safe)
__device__ float g_qkv[(size_t)M_ROWS * 3 * DIM];   // [200704, 1152]
__device__ float g_att[(size_t)M_ROWS * DIM];       // [200704, 384]

// ---------------- f32x2 helpers ----------------
__device__ __forceinline__ unsigned long long dup_f32(float x) {
    unsigned long long r;
    asm("mov.b64 %0, {%1, %1};" : "=l"(r) : "f"(x));
    return r;
}
__device__ __forceinline__ void ffma2(unsigned long long& c,
                                      unsigned long long a,
                                      unsigned long long b) {
    asm("fma.rn.f32x2 %0, %1, %2, %0;" : "+l"(c) : "l"(a), "l"(b));
}
__device__ __forceinline__ void unpack2(unsigned long long v, float& lo, float& hi) {
    asm("mov.b64 {%0, %1}, %2;" : "=f"(lo), "=f"(hi) : "l"(v));
}

// ---------------------------------------------------------------------------
// C[M,N] = A[M,K] * B[N,K]^T + bias[N]     (both operands K-contiguous, "NT")
// BM=BN=128, BK=16, 256 threads, 8x8 per thread via f32x2 packed FMA.
// Requires: M % 128 == 0, N % 128 == 0, K % 16 == 0.
// ---------------------------------------------------------------------------
__global__ __launch_bounds__(256, 2)
void sgemm_nt(const float* __restrict__ A, const float* __restrict__ Bm,
              const float* __restrict__ bias, float* __restrict__ C,
              int M, int N, int K)
{
    __shared__ float As[16][128];
    __shared__ float Bs[16][128];

    const int tid = threadIdx.x;
    const int tx = tid & 15;        // column group (8 cols)
    const int ty = tid >> 4;        // row group (8 rows)
    const int bm = blockIdx.y * 128;
    const int bn = blockIdx.x * 128;

    unsigned long long c2[8][4];
#pragma unroll
    for (int i = 0; i < 8; i++)
#pragma unroll
        for (int j = 0; j < 4; j++) c2[i][j] = 0ull;

    for (int kk = 0; kk < K; kk += 16) {
        // Load 128x16 tiles of A and B, store transposed [k][row]
#pragma unroll
        for (int l = 0; l < 2; l++) {
            int f   = tid + l * 256;      // 0..511 -> 128 rows x 4 float4
            int row = f >> 2;
            int c4  = (f & 3) * 4;
            float4 va = *(const float4*)(A  + (size_t)(bm + row) * K + kk + c4);
            As[c4 + 0][row] = va.x; As[c4 + 1][row] = va.y;
            As[c4 + 2][row] = va.z; As[c4 + 3][row] = va.w;
            float4 vb = *(const float4*)(Bm + (size_t)(bn + row) * K + kk + c4);
            Bs[c4 + 0][row] = vb.x; Bs[c4 + 1][row] = vb.y;
            Bs[c4 + 2][row] = vb.z; Bs[c4 + 3][row] = vb.w;
        }
        __syncthreads();

#pragma unroll
        for (int k = 0; k < 16; k++) {
            unsigned long long b2[4], a2[8];
#pragma unroll
            for (int j = 0; j < 4; j++)
                b2[j] = *(const unsigned long long*)&Bs[k][tx * 8 + j * 2];
#pragma unroll
            for (int i = 0; i < 8; i++)
                a2[i] = dup_f32(As[k][ty * 8 + i]);
#pragma unroll
            for (int i = 0; i < 8; i++)
#pragma unroll
                for (int j = 0; j < 4; j++)
                    ffma2(c2[i][j], a2[i], b2[j]);
        }
        __syncthreads();
    }

    // Epilogue: add bias, store
#pragma unroll
    for (int i = 0; i < 8; i++) {
        int m = bm + ty * 8 + i;
        float* crow = C + (size_t)m * N + bn + tx * 8;
#pragma unroll
        for (int j = 0; j < 4; j++) {
            float lo, hi;
            unpack2(c2[i][j], lo, hi);
            int n = bn + tx * 8 + j * 2;
            float2 o;
            o.x = lo + bias[n];
            o.y = hi + bias[n + 1];
            *(float2*)(crow + j * 2) = o;
        }
    }
}

// ---------------------------------------------------------------------------
// Windowed attention: one block per (head, window).
// q,k,v are slices of g_qkv [200704, 1152]: q at col h*32, k at 384+h*32,
// v at 768+h*32. Output layout [m, h*32+d] (token-major, channel h*hd+d).
// ---------------------------------------------------------------------------
__global__ __launch_bounds__(256)
void attn_kernel(const float* __restrict__ qkv, const float* __restrict__ mask,
                 const float* __restrict__ bias_table, const int* __restrict__ rel_idx,
                 float* __restrict__ out)
{
    const int h = blockIdx.x;      // 0..11
    const int w = blockIdx.y;      // 0..4095
    const int tid = threadIdx.x;

    __shared__ __align__(16) float q[49][32];
    __shared__ __align__(16) float k[49][32];
    __shared__ __align__(16) float v[49][34];   // padded, 8B-aligned rows
    __shared__ float s[49][50];

    const size_t rowbase = (size_t)w * 49 * 1152 + h * 32;
    for (int t = tid; t < 49 * 32; t += 256) {
        int i = t >> 5, d = t & 31;
        const float* p = qkv + rowbase + (size_t)i * 1152 + d;
        q[i][d] = p[0];
        k[i][d] = p[384];
        v[i][d] = p[768];
    }
    __syncthreads();

    const float scale = 0.17677669529663687f;   // 32^-0.5
    const float* mrow = mask + (size_t)(w & 63) * 49 * 49;

    // scores: s[i][j] = scale * <q_i, k_j> + bias[h,i,j] + mask[w%64,i,j]
    for (int e = tid; e < 49 * 49; e += 256) {
        int i = e / 49, j = e - i * 49;
        unsigned long long acc = 0ull;
        const unsigned long long* q2 = (const unsigned long long*)q[i];
        const unsigned long long* k2 = (const unsigned long long*)k[j];
#pragma unroll
        for (int d2 = 0; d2 < 16; d2++) ffma2(acc, q2[d2], k2[d2]);
        float lo, hi;
        unpack2(acc, lo, hi);
        float b = bias_table[rel_idx[e] * NHEAD + h];
        s[i][j] = (lo + hi) * scale + b + mrow[e];
    }
    __syncthreads();

    // row softmax (one warp per row, rows strided by 8)
    const int warp = tid >> 5, lane = tid & 31;
    for (int r = warp; r < 49; r += 8) {
        float x0 = (lane < 49) ? s[r][lane] : -1e30f;
        float x1 = (lane + 32 < 49) ? s[r][lane + 32] : -1e30f;
        float mx = fmaxf(x0, x1);
#pragma unroll
        for (int o = 16; o > 0; o >>= 1)
            mx = fmaxf(mx, __shfl_xor_sync(0xffffffffu, mx, o));
        float e0 = (lane < 49) ? __expf(x0 - mx) : 0.f;
        float e1 = (lane + 32 < 49) ? __expf(x1 - mx) : 0.f;
        float sum = e0 + e1;
#pragma unroll
        for (int o = 16; o > 0; o >>= 1)
            sum += __shfl_xor_sync(0xffffffffu, sum, o);
        float inv = 1.0f / sum;
        if (lane < 49)      s[r][lane]      = e0 * inv;
        if (lane + 32 < 49) s[r][lane + 32] = e1 * inv;
    }
    __syncthreads();

    // out[i, d] = sum_j p[i][j] * v[j][d], packed over d pairs
    for (int e = tid; e < 49 * 16; e += 256) {
        int i = e >> 4, d2 = e & 15;
        unsigned long long acc = 0ull;
#pragma unroll
        for (int j = 0; j < 49; j++) {
            unsigned long long vv = *(const unsigned long long*)&v[j][2 * d2];
            ffma2(acc, dup_f32(s[i][j]), vv);
        }
        float lo, hi;
        unpack2(acc, lo, hi);
        float* op = out + ((size_t)w * 49 + i) * DIM + h * 32 + 2 * d2;
        op[0] = lo;
        op[1] = hi;
    }
}

// ---------------------------------------------------------------------------
extern "C" void kernel_launch(void* const* d_in, const int* in_sizes, int n_in,
                              void* d_out, int out_size)
{
    const float* x          = (const float*)d_in[0];
    const float* mask       = (const float*)d_in[1];
    const float* qkv_w      = (const float*)d_in[2];
    const float* qkv_b      = (const float*)d_in[3];
    const float* proj_w     = (const float*)d_in[4];
    const float* proj_b     = (const float*)d_in[5];
    const float* bias_table = (const float*)d_in[6];
    const int*   rel_idx    = (const int*)d_in[7];
    float* out = (float*)d_out;

    float* qkv_ptr = nullptr;
    float* att_ptr = nullptr;
    cudaGetSymbolAddress((void**)&qkv_ptr, g_qkv);
    cudaGetSymbolAddress((void**)&att_ptr, g_att);

    // 1) qkv = x @ qkv_w^T + qkv_b : [200704, 1152]
    {
        dim3 grid(3 * DIM / 128, M_ROWS / 128);   // 9 x 1568
        sgemm_nt<<<grid, 256>>>(x, qkv_w, qkv_b, qkv_ptr, M_ROWS, 3 * DIM, DIM);
    }
    // 2) attention per (head, window) -> g_att [200704, 384]
    {
        dim3 grid(NHEAD, BWIN);                   // 12 x 4096
        attn_kernel<<<grid, 256>>>(qkv_ptr, mask, bias_table, rel_idx, att_ptr);
    }
    // 3) out = g_att @ proj_w^T + proj_b : [200704, 384]
    {
        dim3 grid(DIM / 128, M_ROWS / 128);       // 3 x 1568
        sgemm_nt<<<grid, 256>>>(att_ptr, proj_w, proj_b, out, M_ROWS, DIM, DIM);
    }
}

// round 4
// speedup vs baseline: 2.9026x; 2.9010x over previous
#include <cuda_runtime.h>
#include <cstdint>

#define DIM     384
#define NHEAD   12
#define NTOK    49
#define BWIN    4096
#define MROWS   (BWIN * NTOK)      // 200704
#define KDIM    384
#define N1      (3 * DIM)          // 1152

// ---------------- static device scratch ----------------
__device__ float g_q[(size_t)MROWS * DIM];
__device__ float g_k[(size_t)MROWS * DIM];
__device__ float g_v[(size_t)MROWS * DIM];
__device__ float g_att[(size_t)MROWS * DIM];
__device__ float g_biasfull[NHEAD * NTOK * NTOK];

// ---------------- helpers ----------------
__device__ __forceinline__ uint32_t s2u(const void* p) {
    uint32_t a;
    asm("{ .reg .u64 t; cvta.to.shared.u64 t, %1; cvt.u32.u64 %0, t; }" : "=r"(a) : "l"(p));
    return a;
}
__device__ __forceinline__ void cpasync16(uint32_t dst, const void* src) {
    asm volatile("cp.async.cg.shared.global [%0], [%1], 16;" :: "r"(dst), "l"(src));
}
__device__ __forceinline__ void cp_commit() {
    asm volatile("cp.async.commit_group;" ::: "memory");
}
__device__ __forceinline__ void cp_wait1() {
    asm volatile("cp.async.wait_group 1;" ::: "memory");
}
__device__ __forceinline__ void cp_wait0() {
    asm volatile("cp.async.wait_group 0;" ::: "memory");
}
__device__ __forceinline__ uint32_t f2tf32(float f) {
    uint32_t u;
    asm("cvt.rna.tf32.f32 %0, %1;" : "=r"(u) : "f"(f));
    return u;
}
__device__ __forceinline__ void mma_tf32(float* c, const uint32_t* a, const uint32_t* b) {
    asm volatile(
        "mma.sync.aligned.m16n8k8.row.col.f32.tf32.tf32.f32 "
        "{%0,%1,%2,%3}, {%4,%5,%6,%7}, {%8,%9}, {%0,%1,%2,%3};"
        : "+f"(c[0]), "+f"(c[1]), "+f"(c[2]), "+f"(c[3])
        : "r"(a[0]), "r"(a[1]), "r"(a[2]), "r"(a[3]), "r"(b[0]), "r"(b[1]));
}

// f32x2 packed FMA (proven on this toolchain)
__device__ __forceinline__ unsigned long long dup_f32(float x) {
    unsigned long long r; asm("mov.b64 %0, {%1, %1};" : "=l"(r) : "f"(x)); return r;
}
__device__ __forceinline__ void ffma2(unsigned long long& c, unsigned long long a, unsigned long long b) {
    asm("fma.rn.f32x2 %0, %1, %2, %0;" : "+l"(c) : "l"(a), "l"(b));
}
__device__ __forceinline__ void unpack2(unsigned long long v, float& lo, float& hi) {
    asm("mov.b64 {%0, %1}, %2;" : "=f"(lo), "=f"(hi) : "l"(v));
}

// ---------------------------------------------------------------------------
// bias_full[h][i*49+j] = bias_table[rel_idx[i*49+j]*12 + h]
// ---------------------------------------------------------------------------
__global__ void bias_pre(const float* __restrict__ bt, const int* __restrict__ rel,
                         float* __restrict__ bf)
{
    for (int t = blockIdx.x * blockDim.x + threadIdx.x; t < NHEAD * NTOK * NTOK;
         t += gridDim.x * blockDim.x) {
        int h = t / (NTOK * NTOK), e = t - h * (NTOK * NTOK);
        bf[t] = bt[rel[e] * NHEAD + h];
    }
}

// ---------------------------------------------------------------------------
// TF32 HMMA GEMM: C[M,N] = A[M,K] * B[N,K]^T + bias  (K=384)
// Block 128x128, chunk BK=32, 8 warps (2m x 4n), warp tile 64x32.
// Smem rows padded to 36 floats -> fragment LDS are bank-conflict-free.
// mode 0: scatter columns into q/k/v head-major [(w*12+h)*49+i][32]
// mode 1: row-major out[m][384]
// ---------------------------------------------------------------------------
#define PAD 36
#define BUFF 4608                // floats per operand buffer: 128*36
#define SMEMB (4 * BUFF * 4)     // 2 stages * (A+B) = 73728 bytes

__global__ __launch_bounds__(256, 2)
void gemm_tf32(const float* __restrict__ A, const float* __restrict__ Bm,
               const float* __restrict__ bias, float* __restrict__ outp,
               float* __restrict__ qo, float* __restrict__ ko, float* __restrict__ vo,
               int mode)
{
    extern __shared__ __align__(16) float sm[];
    const int tid = threadIdx.x;
    const int wid = tid >> 5, lane = tid & 31;
    const int wm = wid & 1, wn = wid >> 1;          // 2 x 4 warp grid
    const int bn = blockIdx.x, bm = blockIdx.y;
    const uint32_t smb = s2u(sm);

    // global load mapping: 8 cp.async per thread per chunk
    const int lrow = tid >> 3;            // 0..31 (+32 per pass)
    const int lcol = (tid & 7) * 4;       // float offset, 16B chunk

    auto issue = [&](int ch) {
        const int st = ch & 1;
        const uint32_t da = smb + (size_t)(st * 2 * BUFF) * 4;
        const uint32_t db = da + BUFF * 4;
        const int kk = ch * 32;
        const float* ga = A  + (size_t)(bm * 128) * KDIM + kk;
        const float* gb = Bm + (size_t)(bn * 128) * KDIM + kk;
#pragma unroll
        for (int p = 0; p < 4; p++) {
            int r = lrow + p * 32;
            cpasync16(da + (r * PAD + lcol) * 4, ga + (size_t)r * KDIM + lcol);
            cpasync16(db + (r * PAD + lcol) * 4, gb + (size_t)r * KDIM + lcol);
        }
        cp_commit();
    };

    float cacc[4][4][4];
#pragma unroll
    for (int i = 0; i < 4; i++)
#pragma unroll
        for (int j = 0; j < 4; j++)
#pragma unroll
            for (int q = 0; q < 4; q++) cacc[i][j][q] = 0.f;

    issue(0);
    const int r4 = lane >> 2, c4 = lane & 3;

    for (int ch = 0; ch < 12; ch++) {
        if (ch + 1 < 12) issue(ch + 1);
        if (ch == 11) cp_wait0(); else cp_wait1();
        __syncthreads();

        const float* As = sm + (ch & 1) * 2 * BUFF;
        const float* Bs = As + BUFF;
#pragma unroll
        for (int k8 = 0; k8 < 4; k8++) {
            uint32_t af[4][4], bf[4][2];
#pragma unroll
            for (int mi = 0; mi < 4; mi++) {
                const float* ap = As + (wm * 64 + mi * 16 + r4) * PAD + k8 * 8 + c4;
                af[mi][0] = f2tf32(ap[0]);
                af[mi][1] = f2tf32(ap[8 * PAD]);
                af[mi][2] = f2tf32(ap[4]);
                af[mi][3] = f2tf32(ap[8 * PAD + 4]);
            }
#pragma unroll
            for (int ni = 0; ni < 4; ni++) {
                const float* bp = Bs + (wn * 32 + ni * 8 + r4) * PAD + k8 * 8 + c4;
                bf[ni][0] = f2tf32(bp[0]);
                bf[ni][1] = f2tf32(bp[4]);
            }
#pragma unroll
            for (int mi = 0; mi < 4; mi++)
#pragma unroll
                for (int ni = 0; ni < 4; ni++)
                    mma_tf32(cacc[mi][ni], af[mi], bf[ni]);
        }
        __syncthreads();
    }

    // ---- epilogue ----
#pragma unroll
    for (int mi = 0; mi < 4; mi++) {
#pragma unroll
        for (int ni = 0; ni < 4; ni++) {
            const int m0 = bm * 128 + wm * 64 + mi * 16 + (lane >> 2);
            const int n0 = bn * 128 + wn * 32 + ni * 8 + 2 * (lane & 3);
            const float b0 = __ldg(bias + n0), b1 = __ldg(bias + n0 + 1);
            float2 v0 = { cacc[mi][ni][0] + b0, cacc[mi][ni][1] + b1 };
            float2 v1 = { cacc[mi][ni][2] + b0, cacc[mi][ni][3] + b1 };
            if (mode == 0) {
                const int arr = n0 / DIM, nin = n0 - arr * DIM;
                const int h = nin >> 5, d = nin & 31;
                float* basep = (arr == 0 ? qo : (arr == 1 ? ko : vo));
                int w0 = m0 / NTOK, i0 = m0 - w0 * NTOK;
                *(float2*)(basep + (((size_t)(w0 * NHEAD + h) * NTOK + i0) << 5) + d) = v0;
                int m1 = m0 + 8;
                int w1 = m1 / NTOK, i1 = m1 - w1 * NTOK;
                *(float2*)(basep + (((size_t)(w1 * NHEAD + h) * NTOK + i1) << 5) + d) = v1;
            } else {
                *(float2*)(outp + (size_t)m0 * DIM + n0) = v0;
                *(float2*)(outp + (size_t)(m0 + 8) * DIM + n0) = v1;
            }
        }
    }
}

// ---------------------------------------------------------------------------
// Attention: one block per (h, w). Head-major contiguous q/k/v.
// k/v rows padded to 34 floats -> <=2-way LDS conflicts.
// ---------------------------------------------------------------------------
__global__ __launch_bounds__(256)
void attn_kernel(const float* __restrict__ qg, const float* __restrict__ kg,
                 const float* __restrict__ vg, const float* __restrict__ mask,
                 const float* __restrict__ biasf, float* __restrict__ out)
{
    const int h = blockIdx.x, w = blockIdx.y, tid = threadIdx.x;
    __shared__ __align__(16) float q[49][32];
    __shared__ __align__(8)  float k[49][34];
    __shared__ __align__(8)  float v[49][34];
    __shared__ float s[49][50];

    const size_t base = ((size_t)(w * NHEAD + h) * NTOK) << 5;
    for (int t = tid; t < 49 * 32; t += 256) {
        int i = t >> 5, d = t & 31;
        q[i][d] = qg[base + t];
        k[i][d] = kg[base + t];
        v[i][d] = vg[base + t];
    }
    __syncthreads();

    const float scale = 0.17677669529663687f;
    const float* mrow = mask + (size_t)(w & 63) * 2401;
    const float* brow = biasf + (size_t)h * 2401;

    for (int e = tid; e < 2401; e += 256) {
        int i = e / 49, j = e - i * 49;
        unsigned long long acc = 0ull;
        const unsigned long long* q2 = (const unsigned long long*)q[i];
        const unsigned long long* k2 = (const unsigned long long*)k[j];
#pragma unroll
        for (int d2 = 0; d2 < 16; d2++) ffma2(acc, q2[d2], k2[d2]);
        float lo, hi; unpack2(acc, lo, hi);
        s[i][j] = (lo + hi) * scale + brow[e] + mrow[e];
    }
    __syncthreads();

    const int warp = tid >> 5, lane = tid & 31;
    for (int r = warp; r < 49; r += 8) {
        float x0 = (lane < 49) ? s[r][lane] : -1e30f;
        float x1 = (lane + 32 < 49) ? s[r][lane + 32] : -1e30f;
        float mx = fmaxf(x0, x1);
#pragma unroll
        for (int o = 16; o > 0; o >>= 1) mx = fmaxf(mx, __shfl_xor_sync(~0u, mx, o));
        float e0 = (lane < 49) ? __expf(x0 - mx) : 0.f;
        float e1 = (lane + 32 < 49) ? __expf(x1 - mx) : 0.f;
        float sum = e0 + e1;
#pragma unroll
        for (int o = 16; o > 0; o >>= 1) sum += __shfl_xor_sync(~0u, sum, o);
        float inv = 1.0f / sum;
        if (lane < 49)      s[r][lane]      = e0 * inv;
        if (lane + 32 < 49) s[r][lane + 32] = e1 * inv;
    }
    __syncthreads();

    for (int e = tid; e < 49 * 16; e += 256) {
        int i = e >> 4, d2 = e & 15;
        unsigned long long acc = 0ull;
#pragma unroll
        for (int j = 0; j < 49; j++) {
            unsigned long long vv = *(const unsigned long long*)&v[j][2 * d2];
            ffma2(acc, dup_f32(s[i][j]), vv);
        }
        float lo, hi; unpack2(acc, lo, hi);
        float* op = out + ((size_t)w * 49 + i) * DIM + h * 32 + 2 * d2;
        op[0] = lo; op[1] = hi;
    }
}

// ---------------------------------------------------------------------------
extern "C" void kernel_launch(void* const* d_in, const int* in_sizes, int n_in,
                              void* d_out, int out_size)
{
    const float* x      = (const float*)d_in[0];
    const float* mask   = (const float*)d_in[1];
    const float* qkv_w  = (const float*)d_in[2];
    const float* qkv_b  = (const float*)d_in[3];
    const float* proj_w = (const float*)d_in[4];
    const float* proj_b = (const float*)d_in[5];
    const float* bt     = (const float*)d_in[6];
    const int*   rel    = (const int*)d_in[7];
    float* out = (float*)d_out;

    float *qp, *kp, *vp, *attp, *bfp;
    cudaGetSymbolAddress((void**)&qp, g_q);
    cudaGetSymbolAddress((void**)&kp, g_k);
    cudaGetSymbolAddress((void**)&vp, g_v);
    cudaGetSymbolAddress((void**)&attp, g_att);
    cudaGetSymbolAddress((void**)&bfp, g_biasfull);

    cudaFuncSetAttribute(gemm_tf32, cudaFuncAttributeMaxDynamicSharedMemorySize, SMEMB);

    bias_pre<<<113, 256>>>(bt, rel, bfp);

    // qkv = x @ qkv_w^T + qkv_b, scattered into head-major q/k/v
    dim3 g1(N1 / 128, MROWS / 128);    // 9 x 1568
    gemm_tf32<<<g1, 256, SMEMB>>>(x, qkv_w, qkv_b, nullptr, qp, kp, vp, 0);

    dim3 ga(NHEAD, BWIN);              // 12 x 4096
    attn_kernel<<<ga, 256>>>(qp, kp, vp, mask, bfp, attp);

    // out = att @ proj_w^T + proj_b
    dim3 g2(DIM / 128, MROWS / 128);   // 3 x 1568
    gemm_tf32<<<g2, 256, SMEMB>>>(attp, proj_w, proj_b, out, nullptr, nullptr, nullptr, 1);
}

// round 5
// speedup vs baseline: 3.7877x; 1.3049x over previous
#include <cuda_runtime.h>
#include <cstdint>

#define DIM     384
#define NHEAD   12
#define NTOK    49
#define BWIN    4096
#define MROWS   (BWIN * NTOK)      // 200704
#define KDIM    384
#define N1      (3 * DIM)          // 1152

// ---------------- static device scratch ----------------
__device__ float g_q[(size_t)MROWS * DIM];
__device__ float g_k[(size_t)MROWS * DIM];
__device__ float g_v[(size_t)MROWS * DIM];
__device__ float g_att[(size_t)MROWS * DIM];
__device__ float g_biasfull[NHEAD * NTOK * NTOK];

// ---------------- helpers ----------------
__device__ __forceinline__ uint32_t s2u(const void* p) {
    uint32_t a;
    asm("{ .reg .u64 t; cvta.to.shared.u64 t, %1; cvt.u32.u64 %0, t; }" : "=r"(a) : "l"(p));
    return a;
}
__device__ __forceinline__ void cpasync16(uint32_t dst, const void* src) {
    asm volatile("cp.async.cg.shared.global [%0], [%1], 16;" :: "r"(dst), "l"(src));
}
__device__ __forceinline__ void cp_commit() { asm volatile("cp.async.commit_group;" ::: "memory"); }
__device__ __forceinline__ void cp_wait1()  { asm volatile("cp.async.wait_group 1;" ::: "memory"); }
__device__ __forceinline__ void cp_wait0()  { asm volatile("cp.async.wait_group 0;" ::: "memory"); }
__device__ __forceinline__ uint32_t f2tf32(float f) {
    uint32_t u;
    asm("cvt.rna.tf32.f32 %0, %1;" : "=r"(u) : "f"(f));
    return u;
}
__device__ __forceinline__ void mma_tf32(float* c, const uint32_t* a, const uint32_t* b) {
    asm volatile(
        "mma.sync.aligned.m16n8k8.row.col.f32.tf32.tf32.f32 "
        "{%0,%1,%2,%3}, {%4,%5,%6,%7}, {%8,%9}, {%0,%1,%2,%3};"
        : "+f"(c[0]), "+f"(c[1]), "+f"(c[2]), "+f"(c[3])
        : "r"(a[0]), "r"(a[1]), "r"(a[2]), "r"(a[3]), "r"(b[0]), "r"(b[1]));
}

// ---------------------------------------------------------------------------
// bias_full[h][i*49+j] = bias_table[rel_idx[i*49+j]*12 + h]
// ---------------------------------------------------------------------------
__global__ void bias_pre(const float* __restrict__ bt, const int* __restrict__ rel,
                         float* __restrict__ bf)
{
    for (int t = blockIdx.x * blockDim.x + threadIdx.x; t < NHEAD * NTOK * NTOK;
         t += gridDim.x * blockDim.x) {
        int h = t / (NTOK * NTOK), e = t - h * (NTOK * NTOK);
        bf[t] = bt[rel[e] * NHEAD + h];
    }
}

// ---------------------------------------------------------------------------
// TF32 HMMA GEMM (unchanged from R4, proven): C = A * B^T + bias
// ---------------------------------------------------------------------------
#define PAD 36
#define BUFF 4608
#define SMEMB (4 * BUFF * 4)

__global__ __launch_bounds__(256, 2)
void gemm_tf32(const float* __restrict__ A, const float* __restrict__ Bm,
               const float* __restrict__ bias, float* __restrict__ outp,
               float* __restrict__ qo, float* __restrict__ ko, float* __restrict__ vo,
               int mode)
{
    extern __shared__ __align__(16) float sm[];
    const int tid = threadIdx.x;
    const int wid = tid >> 5, lane = tid & 31;
    const int wm = wid & 1, wn = wid >> 1;
    const int bn = blockIdx.x, bm = blockIdx.y;
    const uint32_t smb = s2u(sm);

    const int lrow = tid >> 3;
    const int lcol = (tid & 7) * 4;

    auto issue = [&](int ch) {
        const int st = ch & 1;
        const uint32_t da = smb + (size_t)(st * 2 * BUFF) * 4;
        const uint32_t db = da + BUFF * 4;
        const int kk = ch * 32;
        const float* ga = A  + (size_t)(bm * 128) * KDIM + kk;
        const float* gb = Bm + (size_t)(bn * 128) * KDIM + kk;
#pragma unroll
        for (int p = 0; p < 4; p++) {
            int r = lrow + p * 32;
            cpasync16(da + (r * PAD + lcol) * 4, ga + (size_t)r * KDIM + lcol);
            cpasync16(db + (r * PAD + lcol) * 4, gb + (size_t)r * KDIM + lcol);
        }
        cp_commit();
    };

    float cacc[4][4][4];
#pragma unroll
    for (int i = 0; i < 4; i++)
#pragma unroll
        for (int j = 0; j < 4; j++)
#pragma unroll
            for (int q = 0; q < 4; q++) cacc[i][j][q] = 0.f;

    issue(0);
    const int r4 = lane >> 2, c4 = lane & 3;

    for (int ch = 0; ch < 12; ch++) {
        if (ch + 1 < 12) issue(ch + 1);
        if (ch == 11) cp_wait0(); else cp_wait1();
        __syncthreads();

        const float* As = sm + (ch & 1) * 2 * BUFF;
        const float* Bs = As + BUFF;
#pragma unroll
        for (int k8 = 0; k8 < 4; k8++) {
            uint32_t af[4][4], bf[4][2];
#pragma unroll
            for (int mi = 0; mi < 4; mi++) {
                const float* ap = As + (wm * 64 + mi * 16 + r4) * PAD + k8 * 8 + c4;
                af[mi][0] = f2tf32(ap[0]);
                af[mi][1] = f2tf32(ap[8 * PAD]);
                af[mi][2] = f2tf32(ap[4]);
                af[mi][3] = f2tf32(ap[8 * PAD + 4]);
            }
#pragma unroll
            for (int ni = 0; ni < 4; ni++) {
                const float* bp = Bs + (wn * 32 + ni * 8 + r4) * PAD + k8 * 8 + c4;
                bf[ni][0] = f2tf32(bp[0]);
                bf[ni][1] = f2tf32(bp[4]);
            }
#pragma unroll
            for (int mi = 0; mi < 4; mi++)
#pragma unroll
                for (int ni = 0; ni < 4; ni++)
                    mma_tf32(cacc[mi][ni], af[mi], bf[ni]);
        }
        __syncthreads();
    }

#pragma unroll
    for (int mi = 0; mi < 4; mi++) {
#pragma unroll
        for (int ni = 0; ni < 4; ni++) {
            const int m0 = bm * 128 + wm * 64 + mi * 16 + (lane >> 2);
            const int n0 = bn * 128 + wn * 32 + ni * 8 + 2 * (lane & 3);
            const float b0 = __ldg(bias + n0), b1 = __ldg(bias + n0 + 1);
            float2 v0 = { cacc[mi][ni][0] + b0, cacc[mi][ni][1] + b1 };
            float2 v1 = { cacc[mi][ni][2] + b0, cacc[mi][ni][3] + b1 };
            if (mode == 0) {
                const int arr = n0 / DIM, nin = n0 - arr * DIM;
                const int h = nin >> 5, d = nin & 31;
                float* basep = (arr == 0 ? qo : (arr == 1 ? ko : vo));
                int w0 = m0 / NTOK, i0 = m0 - w0 * NTOK;
                *(float2*)(basep + (((size_t)(w0 * NHEAD + h) * NTOK + i0) << 5) + d) = v0;
                int m1 = m0 + 8;
                int w1 = m1 / NTOK, i1 = m1 - w1 * NTOK;
                *(float2*)(basep + (((size_t)(w1 * NHEAD + h) * NTOK + i1) << 5) + d) = v1;
            } else {
                *(float2*)(outp + (size_t)m0 * DIM + n0) = v0;
                *(float2*)(outp + (size_t)(m0 + 8) * DIM + n0) = v1;
            }
        }
    }
}

// ---------------------------------------------------------------------------
// MMA attention: one block per (h, w), 128 threads (4 warps), 49 padded to 64.
//   ss preloaded with bias+mask; S = Q K^T (TF32 MMA); softmax; O = P V.
// ---------------------------------------------------------------------------
#define QP 36
#define SP 68

__global__ __launch_bounds__(128)
void attn_mma(const float* __restrict__ qg, const float* __restrict__ kg,
              const float* __restrict__ vg, const float* __restrict__ mask,
              const float* __restrict__ biasf, float* __restrict__ out)
{
    const int h = blockIdx.x, w = blockIdx.y, tid = threadIdx.x;
    const int wid = tid >> 5, lane = tid & 31;
    const int r4 = lane >> 2, c4 = lane & 3;

    __shared__ __align__(16) float qs[64][QP];
    __shared__ __align__(16) float ks[64][QP];
    __shared__ __align__(16) float vt[32][SP];
    __shared__ __align__(16) float ss[64][SP];

    // zero pads: q/k rows 49..63, vt cols 49..63
    for (int t = tid; t < 15 * QP; t += 128) {
        int r = t / QP, c = t - r * QP;
        qs[49 + r][c] = 0.f;
        ks[49 + r][c] = 0.f;
    }
    for (int t = tid; t < 32 * 15; t += 128) {
        int d = t / 15, j = t - d * 15;
        vt[d][49 + j] = 0.f;
    }

    // load q/k/v (coalesced) + preload ss = bias + mask
    const size_t base = ((size_t)(w * NHEAD + h) * NTOK) << 5;
    for (int t = tid; t < 49 * 32; t += 128) {
        int i = t >> 5, d = t & 31;
        qs[i][d] = qg[base + t];
        ks[i][d] = kg[base + t];
        vt[d][i] = vg[base + t];
    }
    const float* mrow = mask + (size_t)(w & 63) * 2401;
    const float* brow = biasf + (size_t)h * 2401;
    for (int e = tid; e < 2401; e += 128) {
        int i = e / 49, j = e - i * 49;
        ss[i][j] = brow[e] + mrow[e];
    }
    __syncthreads();

    // ---- S = Q K^T : warp computes rows [wid*16, +16) x cols [0,64) ----
    const int m0 = wid * 16;
    {
        float sacc[8][4];
#pragma unroll
        for (int ni = 0; ni < 8; ni++)
#pragma unroll
            for (int q = 0; q < 4; q++) sacc[ni][q] = 0.f;

#pragma unroll
        for (int k8 = 0; k8 < 4; k8++) {
            uint32_t af[4];
            const float* ap = &qs[m0 + r4][k8 * 8 + c4];
            af[0] = f2tf32(ap[0]);
            af[1] = f2tf32(ap[8 * QP]);
            af[2] = f2tf32(ap[4]);
            af[3] = f2tf32(ap[8 * QP + 4]);
#pragma unroll
            for (int ni = 0; ni < 8; ni++) {
                uint32_t bf[2];
                const float* bp = &ks[ni * 8 + r4][k8 * 8 + c4];
                bf[0] = f2tf32(bp[0]);
                bf[1] = f2tf32(bp[4]);
                mma_tf32(sacc[ni], af, bf);
            }
        }

        const float scale = 0.17677669529663687f;   // 32^-0.5
        const int i0 = m0 + r4;
#pragma unroll
        for (int ni = 0; ni < 8; ni++) {
            const int j0 = ni * 8 + 2 * c4;
            if (i0 < 49) {
                if (j0 < 49)     ss[i0][j0]     = sacc[ni][0] * scale + ss[i0][j0];
                if (j0 + 1 < 49) ss[i0][j0 + 1] = sacc[ni][1] * scale + ss[i0][j0 + 1];
            }
            if (i0 + 8 < 49) {
                if (j0 < 49)     ss[i0 + 8][j0]     = sacc[ni][2] * scale + ss[i0 + 8][j0];
                if (j0 + 1 < 49) ss[i0 + 8][j0 + 1] = sacc[ni][3] * scale + ss[i0 + 8][j0 + 1];
            }
        }
    }
    __syncthreads();

    // ---- softmax rows (warp per row, stride 4); zero pad cols 49..63 ----
    for (int r = wid; r < 49; r += 4) {
        float x0 = ss[r][lane];
        float x1 = (lane + 32 < 49) ? ss[r][lane + 32] : -1e30f;
        float mx = fmaxf(x0, x1);
#pragma unroll
        for (int o = 16; o > 0; o >>= 1) mx = fmaxf(mx, __shfl_xor_sync(~0u, mx, o));
        float e0 = __expf(x0 - mx);
        float e1 = (lane + 32 < 49) ? __expf(x1 - mx) : 0.f;
        float sum = e0 + e1;
#pragma unroll
        for (int o = 16; o > 0; o >>= 1) sum += __shfl_xor_sync(~0u, sum, o);
        float inv = 1.0f / sum;
        ss[r][lane] = e0 * inv;
        ss[r][lane + 32] = e1 * inv;        // cols 49..63 get 0
    }
    __syncthreads();

    // ---- O = P V : warp computes rows [m0, +16) x d [0,32) ----
    {
        float oacc[4][4];
#pragma unroll
        for (int ni = 0; ni < 4; ni++)
#pragma unroll
            for (int q = 0; q < 4; q++) oacc[ni][q] = 0.f;

#pragma unroll
        for (int k8 = 0; k8 < 8; k8++) {
            uint32_t af[4];
            const float* ap = &ss[m0 + r4][k8 * 8 + c4];
            af[0] = f2tf32(ap[0]);
            af[1] = f2tf32(ap[8 * SP]);
            af[2] = f2tf32(ap[4]);
            af[3] = f2tf32(ap[8 * SP + 4]);
#pragma unroll
            for (int ni = 0; ni < 4; ni++) {
                uint32_t bf[2];
                const float* bp = &vt[ni * 8 + r4][k8 * 8 + c4];
                bf[0] = f2tf32(bp[0]);
                bf[1] = f2tf32(bp[4]);
                mma_tf32(oacc[ni], af, bf);
            }
        }

        const int i0 = m0 + r4;
#pragma unroll
        for (int ni = 0; ni < 4; ni++) {
            const int d0 = ni * 8 + 2 * c4;
            if (i0 < 49) {
                float2 o0 = { oacc[ni][0], oacc[ni][1] };
                *(float2*)(out + ((size_t)w * 49 + i0) * DIM + h * 32 + d0) = o0;
            }
            if (i0 + 8 < 49) {
                float2 o1 = { oacc[ni][2], oacc[ni][3] };
                *(float2*)(out + ((size_t)w * 49 + i0 + 8) * DIM + h * 32 + d0) = o1;
            }
        }
    }
}

// ---------------------------------------------------------------------------
extern "C" void kernel_launch(void* const* d_in, const int* in_sizes, int n_in,
                              void* d_out, int out_size)
{
    const float* x      = (const float*)d_in[0];
    const float* mask   = (const float*)d_in[1];
    const float* qkv_w  = (const float*)d_in[2];
    const float* qkv_b  = (const float*)d_in[3];
    const float* proj_w = (const float*)d_in[4];
    const float* proj_b = (const float*)d_in[5];
    const float* bt     = (const float*)d_in[6];
    const int*   rel    = (const int*)d_in[7];
    float* out = (float*)d_out;

    float *qp, *kp, *vp, *attp, *bfp;
    cudaGetSymbolAddress((void**)&qp, g_q);
    cudaGetSymbolAddress((void**)&kp, g_k);
    cudaGetSymbolAddress((void**)&vp, g_v);
    cudaGetSymbolAddress((void**)&attp, g_att);
    cudaGetSymbolAddress((void**)&bfp, g_biasfull);

    cudaFuncSetAttribute(gemm_tf32, cudaFuncAttributeMaxDynamicSharedMemorySize, SMEMB);

    bias_pre<<<113, 256>>>(bt, rel, bfp);

    dim3 g1(N1 / 128, MROWS / 128);    // 9 x 1568
    gemm_tf32<<<g1, 256, SMEMB>>>(x, qkv_w, qkv_b, nullptr, qp, kp, vp, 0);

    dim3 ga(NHEAD, BWIN);              // 12 x 4096
    attn_mma<<<ga, 128>>>(qp, kp, vp, mask, bfp, attp);

    dim3 g2(DIM / 128, MROWS / 128);   // 3 x 1568
    gemm_tf32<<<g2, 256, SMEMB>>>(attp, proj_w, proj_b, out, nullptr, nullptr, nullptr, 1);
}

// round 6
// speedup vs baseline: 3.9043x; 1.0308x over previous
#include <cuda_runtime.h>
#include <cstdint>

#define DIM     384
#define NHEAD   12
#define NTOK    49
#define BWIN    4096
#define MROWS   (BWIN * NTOK)      // 200704
#define KDIM    384
#define N1      (3 * DIM)          // 1152

// ---------------- static device scratch ----------------
__device__ float g_q[(size_t)MROWS * DIM];
__device__ float g_k[(size_t)MROWS * DIM];
__device__ float g_v[(size_t)MROWS * DIM];
__device__ float g_att[(size_t)MROWS * DIM];
__device__ float g_xr[(size_t)MROWS * DIM];
__device__ float g_w1r[(size_t)N1 * KDIM];
__device__ float g_w2r[(size_t)DIM * KDIM];
__device__ float g_biasfull[NHEAD * NTOK * NTOK];

// ---------------- helpers ----------------
__device__ __forceinline__ uint32_t s2u(const void* p) {
    uint32_t a;
    asm("{ .reg .u64 t; cvta.to.shared.u64 t, %1; cvt.u32.u64 %0, t; }" : "=r"(a) : "l"(p));
    return a;
}
__device__ __forceinline__ void cpasync16(uint32_t dst, const void* src) {
    asm volatile("cp.async.cg.shared.global [%0], [%1], 16;" :: "r"(dst), "l"(src));
}
__device__ __forceinline__ void cp_commit() { asm volatile("cp.async.commit_group;" ::: "memory"); }
__device__ __forceinline__ void cp_wait1()  { asm volatile("cp.async.wait_group 1;" ::: "memory"); }
__device__ __forceinline__ void cp_wait0()  { asm volatile("cp.async.wait_group 0;" ::: "memory"); }
__device__ __forceinline__ uint32_t f2tf32(float f) {
    uint32_t u;
    asm("cvt.rna.tf32.f32 %0, %1;" : "=r"(u) : "f"(f));
    return u;
}
__device__ __forceinline__ float rnd_tf32(float f) {
    return __uint_as_float(f2tf32(f));
}
__device__ __forceinline__ void mma_tf32(float* c, const uint32_t* a, const uint32_t* b) {
    asm volatile(
        "mma.sync.aligned.m16n8k8.row.col.f32.tf32.tf32.f32 "
        "{%0,%1,%2,%3}, {%4,%5,%6,%7}, {%8,%9}, {%0,%1,%2,%3};"
        : "+f"(c[0]), "+f"(c[1]), "+f"(c[2]), "+f"(c[3])
        : "r"(a[0]), "r"(a[1]), "r"(a[2]), "r"(a[3]), "r"(b[0]), "r"(b[1]));
}

// ---------------------------------------------------------------------------
// Pre-round fp32 -> tf32-bit floats (vectorized, grid-stride)
// ---------------------------------------------------------------------------
__global__ void round_pass(const float* __restrict__ in, float* __restrict__ outp, size_t n4)
{
    for (size_t i = blockIdx.x * blockDim.x + threadIdx.x; i < n4;
         i += (size_t)gridDim.x * blockDim.x) {
        float4 v = ((const float4*)in)[i];
        v.x = rnd_tf32(v.x); v.y = rnd_tf32(v.y);
        v.z = rnd_tf32(v.z); v.w = rnd_tf32(v.w);
        ((float4*)outp)[i] = v;
    }
}

// ---------------------------------------------------------------------------
// bias_full[h][i*49+j] = bias_table[rel_idx[i*49+j]*12 + h]
// ---------------------------------------------------------------------------
__global__ void bias_pre(const float* __restrict__ bt, const int* __restrict__ rel,
                         float* __restrict__ bf)
{
    for (int t = blockIdx.x * blockDim.x + threadIdx.x; t < NHEAD * NTOK * NTOK;
         t += gridDim.x * blockDim.x) {
        int h = t / (NTOK * NTOK), e = t - h * (NTOK * NTOK);
        bf[t] = bt[rel[e] * NHEAD + h];
    }
}

// ---------------------------------------------------------------------------
// TF32 HMMA GEMM: C = A * B^T + bias.  A,B hold PRE-ROUNDED tf32 floats,
// so fragments are raw u32 loads (no cvt in the hot loop).
// mode 0: scatter into q (scaled+rounded) / k (rounded) / v (rounded)
// mode 1: row-major final output (no rounding)
// ---------------------------------------------------------------------------
#define PAD 36
#define BUFF 4608
#define SMEMB (4 * BUFF * 4)

__global__ __launch_bounds__(256, 2)
void gemm_tf32(const float* __restrict__ A, const float* __restrict__ Bm,
               const float* __restrict__ bias, float* __restrict__ outp,
               float* __restrict__ qo, float* __restrict__ ko, float* __restrict__ vo,
               int mode)
{
    extern __shared__ __align__(16) float sm[];
    const int tid = threadIdx.x;
    const int wid = tid >> 5, lane = tid & 31;
    const int wm = wid & 1, wn = wid >> 1;
    const int bn = blockIdx.x, bm = blockIdx.y;
    const uint32_t smb = s2u(sm);

    const int lrow = tid >> 3;
    const int lcol = (tid & 7) * 4;

    auto issue = [&](int ch) {
        const int st = ch & 1;
        const uint32_t da = smb + (size_t)(st * 2 * BUFF) * 4;
        const uint32_t db = da + BUFF * 4;
        const int kk = ch * 32;
        const float* ga = A  + (size_t)(bm * 128) * KDIM + kk;
        const float* gb = Bm + (size_t)(bn * 128) * KDIM + kk;
#pragma unroll
        for (int p = 0; p < 4; p++) {
            int r = lrow + p * 32;
            cpasync16(da + (r * PAD + lcol) * 4, ga + (size_t)r * KDIM + lcol);
            cpasync16(db + (r * PAD + lcol) * 4, gb + (size_t)r * KDIM + lcol);
        }
        cp_commit();
    };

    float cacc[4][4][4];
#pragma unroll
    for (int i = 0; i < 4; i++)
#pragma unroll
        for (int j = 0; j < 4; j++)
#pragma unroll
            for (int q = 0; q < 4; q++) cacc[i][j][q] = 0.f;

    issue(0);
    const int r4 = lane >> 2, c4 = lane & 3;

    for (int ch = 0; ch < 12; ch++) {
        if (ch + 1 < 12) issue(ch + 1);
        if (ch == 11) cp_wait0(); else cp_wait1();
        __syncthreads();

        const float* As = sm + (ch & 1) * 2 * BUFF;
        const float* Bs = As + BUFF;
#pragma unroll
        for (int k8 = 0; k8 < 4; k8++) {
            uint32_t af[4][4], bf[4][2];
#pragma unroll
            for (int mi = 0; mi < 4; mi++) {
                const uint32_t* ap = (const uint32_t*)(As + (wm * 64 + mi * 16 + r4) * PAD + k8 * 8 + c4);
                af[mi][0] = ap[0];
                af[mi][1] = ap[8 * PAD];
                af[mi][2] = ap[4];
                af[mi][3] = ap[8 * PAD + 4];
            }
#pragma unroll
            for (int ni = 0; ni < 4; ni++) {
                const uint32_t* bp = (const uint32_t*)(Bs + (wn * 32 + ni * 8 + r4) * PAD + k8 * 8 + c4);
                bf[ni][0] = bp[0];
                bf[ni][1] = bp[4];
            }
#pragma unroll
            for (int mi = 0; mi < 4; mi++)
#pragma unroll
                for (int ni = 0; ni < 4; ni++)
                    mma_tf32(cacc[mi][ni], af[mi], bf[ni]);
        }
        __syncthreads();
    }

    const float qscale = 0.17677669529663687f;   // 32^-0.5, folded into q
#pragma unroll
    for (int mi = 0; mi < 4; mi++) {
#pragma unroll
        for (int ni = 0; ni < 4; ni++) {
            const int m0 = bm * 128 + wm * 64 + mi * 16 + (lane >> 2);
            const int n0 = bn * 128 + wn * 32 + ni * 8 + 2 * (lane & 3);
            const float b0 = __ldg(bias + n0), b1 = __ldg(bias + n0 + 1);
            float2 v0 = { cacc[mi][ni][0] + b0, cacc[mi][ni][1] + b1 };
            float2 v1 = { cacc[mi][ni][2] + b0, cacc[mi][ni][3] + b1 };
            if (mode == 0) {
                const int arr = n0 / DIM, nin = n0 - arr * DIM;
                const int h = nin >> 5, d = nin & 31;
                if (arr == 0) { v0.x *= qscale; v0.y *= qscale; v1.x *= qscale; v1.y *= qscale; }
                v0.x = rnd_tf32(v0.x); v0.y = rnd_tf32(v0.y);
                v1.x = rnd_tf32(v1.x); v1.y = rnd_tf32(v1.y);
                float* basep = (arr == 0 ? qo : (arr == 1 ? ko : vo));
                int w0 = m0 / NTOK, i0 = m0 - w0 * NTOK;
                *(float2*)(basep + (((size_t)(w0 * NHEAD + h) * NTOK + i0) << 5) + d) = v0;
                int m1 = m0 + 8;
                int w1 = m1 / NTOK, i1 = m1 - w1 * NTOK;
                *(float2*)(basep + (((size_t)(w1 * NHEAD + h) * NTOK + i1) << 5) + d) = v1;
            } else {
                *(float2*)(outp + (size_t)m0 * DIM + n0) = v0;
                *(float2*)(outp + (size_t)(m0 + 8) * DIM + n0) = v1;
            }
        }
    }
}

// ---------------------------------------------------------------------------
// MMA attention: block per (h, w), 4 warps. q pre-scaled; q/k/v pre-rounded.
// No cvt anywhere in the block except P rounding during softmax store.
// ---------------------------------------------------------------------------
#define QP 36
#define SP 69    // ss row stride: 69 % 32 = 5 (coprime) -> conflict-free rows
#define VP 68

__global__ __launch_bounds__(128)
void attn_mma(const float* __restrict__ qg, const float* __restrict__ kg,
              const float* __restrict__ vg, const float* __restrict__ mask,
              const float* __restrict__ biasf, float* __restrict__ out)
{
    const int h = blockIdx.x, w = blockIdx.y, tid = threadIdx.x;
    const int wid = tid >> 5, lane = tid & 31;
    const int r4 = lane >> 2, c4 = lane & 3;

    __shared__ __align__(16) float qs[64][QP];
    __shared__ __align__(16) float ks[64][QP];
    __shared__ __align__(16) float vt[32][VP];
    __shared__ __align__(16) float ss[64][SP];

    // zero: q/k pad rows, vt pad cols, entire ss
    for (int t = tid; t < 15 * QP; t += 128) {
        int r = t / QP, c = t - r * QP;
        qs[49 + r][c] = 0.f;
        ks[49 + r][c] = 0.f;
    }
    for (int t = tid; t < 32 * 15; t += 128) {
        int d = t / 15, j = t - d * 15;
        vt[d][49 + j] = 0.f;
    }
    for (int t = tid; t < 64 * SP; t += 128)
        ((float*)ss)[t] = 0.f;

    const size_t base = ((size_t)(w * NHEAD + h) * NTOK) << 5;
    for (int t = tid; t < 49 * 32; t += 128) {
        int i = t >> 5, d = t & 31;
        qs[i][d] = qg[base + t];
        ks[i][d] = kg[base + t];
        vt[d][i] = vg[base + t];
    }
    const float* mrow = mask + (size_t)(w & 63) * 2401;
    const float* brow = biasf + (size_t)h * 2401;
    for (int e = tid; e < 2401; e += 128) {
        int i = e / 49, j = e - i * 49;
        ss[i][j] = brow[e] + mrow[e];
    }
    __syncthreads();

    // ---- S = Q K^T (q pre-scaled) ----
    const int m0 = wid * 16;
    {
        float sacc[8][4];
#pragma unroll
        for (int ni = 0; ni < 8; ni++)
#pragma unroll
            for (int q = 0; q < 4; q++) sacc[ni][q] = 0.f;

#pragma unroll
        for (int k8 = 0; k8 < 4; k8++) {
            uint32_t af[4];
            const uint32_t* ap = (const uint32_t*)&qs[m0 + r4][k8 * 8 + c4];
            af[0] = ap[0];
            af[1] = ap[8 * QP];
            af[2] = ap[4];
            af[3] = ap[8 * QP + 4];
#pragma unroll
            for (int ni = 0; ni < 8; ni++) {
                uint32_t bf[2];
                const uint32_t* bp = (const uint32_t*)&ks[ni * 8 + r4][k8 * 8 + c4];
                bf[0] = bp[0];
                bf[1] = bp[4];
                mma_tf32(sacc[ni], af, bf);
            }
        }
        const int i0 = m0 + r4;
#pragma unroll
        for (int ni = 0; ni < 8; ni++) {
            const int j0 = ni * 8 + 2 * c4;
            ss[i0][j0]         += sacc[ni][0];
            ss[i0][j0 + 1]     += sacc[ni][1];
            ss[i0 + 8][j0]     += sacc[ni][2];
            ss[i0 + 8][j0 + 1] += sacc[ni][3];
        }
    }
    __syncthreads();

    // ---- softmax: thread-per-row, no shuffles ----
    if (tid < 49) {
        const int r = tid;
        float mx = -1e30f;
#pragma unroll 7
        for (int j = 0; j < 49; j++) mx = fmaxf(mx, ss[r][j]);
        float sum = 0.f;
#pragma unroll 7
        for (int j = 0; j < 49; j++) {
            float e = __expf(ss[r][j] - mx);
            sum += e;
            ss[r][j] = e;
        }
        const float inv = 1.0f / sum;
#pragma unroll 7
        for (int j = 0; j < 49; j++)
            ss[r][j] = rnd_tf32(ss[r][j] * inv);
    }
    __syncthreads();

    // ---- O = P V ----
    {
        float oacc[4][4];
#pragma unroll
        for (int ni = 0; ni < 4; ni++)
#pragma unroll
            for (int q = 0; q < 4; q++) oacc[ni][q] = 0.f;

#pragma unroll
        for (int k8 = 0; k8 < 8; k8++) {
            uint32_t af[4];
            const uint32_t* ap = (const uint32_t*)&ss[m0 + r4][k8 * 8 + c4];
            af[0] = ap[0];
            af[1] = ap[8 * SP];
            af[2] = ap[4];
            af[3] = ap[8 * SP + 4];
#pragma unroll
            for (int ni = 0; ni < 4; ni++) {
                uint32_t bf[2];
                const uint32_t* bp = (const uint32_t*)&vt[ni * 8 + r4][k8 * 8 + c4];
                bf[0] = bp[0];
                bf[1] = bp[4];
                mma_tf32(oacc[ni], af, bf);
            }
        }

        const int i0 = m0 + r4;
#pragma unroll
        for (int ni = 0; ni < 4; ni++) {
            const int d0 = ni * 8 + 2 * c4;
            if (i0 < 49) {
                float2 o0 = { rnd_tf32(oacc[ni][0]), rnd_tf32(oacc[ni][1]) };
                *(float2*)(out + ((size_t)w * 49 + i0) * DIM + h * 32 + d0) = o0;
            }
            if (i0 + 8 < 49) {
                float2 o1 = { rnd_tf32(oacc[ni][2]), rnd_tf32(oacc[ni][3]) };
                *(float2*)(out + ((size_t)w * 49 + i0 + 8) * DIM + h * 32 + d0) = o1;
            }
        }
    }
}

// ---------------------------------------------------------------------------
extern "C" void kernel_launch(void* const* d_in, const int* in_sizes, int n_in,
                              void* d_out, int out_size)
{
    const float* x      = (const float*)d_in[0];
    const float* mask   = (const float*)d_in[1];
    const float* qkv_w  = (const float*)d_in[2];
    const float* qkv_b  = (const float*)d_in[3];
    const float* proj_w = (const float*)d_in[4];
    const float* proj_b = (const float*)d_in[5];
    const float* bt     = (const float*)d_in[6];
    const int*   rel    = (const int*)d_in[7];
    float* out = (float*)d_out;

    float *qp, *kp, *vp, *attp, *bfp, *xr, *w1r, *w2r;
    cudaGetSymbolAddress((void**)&qp, g_q);
    cudaGetSymbolAddress((void**)&kp, g_k);
    cudaGetSymbolAddress((void**)&vp, g_v);
    cudaGetSymbolAddress((void**)&attp, g_att);
    cudaGetSymbolAddress((void**)&bfp, g_biasfull);
    cudaGetSymbolAddress((void**)&xr, g_xr);
    cudaGetSymbolAddress((void**)&w1r, g_w1r);
    cudaGetSymbolAddress((void**)&w2r, g_w2r);

    cudaFuncSetAttribute(gemm_tf32, cudaFuncAttributeMaxDynamicSharedMemorySize, SMEMB);

    // pre-round operands to tf32 bits
    round_pass<<<1184, 256>>>(x, xr, (size_t)MROWS * DIM / 4);
    round_pass<<<112, 256>>>(qkv_w, w1r, (size_t)N1 * KDIM / 4);
    round_pass<<<48, 256>>>(proj_w, w2r, (size_t)DIM * KDIM / 4);
    bias_pre<<<113, 256>>>(bt, rel, bfp);

    dim3 g1(N1 / 128, MROWS / 128);    // 9 x 1568
    gemm_tf32<<<g1, 256, SMEMB>>>(xr, w1r, qkv_b, nullptr, qp, kp, vp, 0);

    dim3 ga(NHEAD, BWIN);              // 12 x 4096
    attn_mma<<<ga, 128>>>(qp, kp, vp, mask, bfp, attp);

    dim3 g2(DIM / 128, MROWS / 128);   // 3 x 1568
    gemm_tf32<<<g2, 256, SMEMB>>>(attp, w2r, proj_b, out, nullptr, nullptr, nullptr, 1);
}

// round 7
// speedup vs baseline: 4.2577x; 1.0905x over previous
#include <cuda_runtime.h>
#include <cstdint>

#define DIM     384
#define NHEAD   12
#define NTOK    49
#define BWIN    4096
#define MROWS   (BWIN * NTOK)      // 200704
#define KDIM    384
#define N1      (3 * DIM)          // 1152

// ---------------- static device scratch ----------------
__device__ float g_q[(size_t)MROWS * DIM];
__device__ float g_k[(size_t)MROWS * DIM];
__device__ float g_v[(size_t)MROWS * DIM];
__device__ float g_att[(size_t)MROWS * DIM];
__device__ float g_xr[(size_t)MROWS * DIM];
__device__ float g_w1r[(size_t)N1 * KDIM];
__device__ float g_w2r[(size_t)DIM * KDIM];
__device__ float g_comb[(size_t)NHEAD * 64 * 64 * 64];   // bias+mask, padded

// ---------------- helpers ----------------
__device__ __forceinline__ uint32_t s2u(const void* p) {
    uint32_t a;
    asm("{ .reg .u64 t; cvta.to.shared.u64 t, %1; cvt.u32.u64 %0, t; }" : "=r"(a) : "l"(p));
    return a;
}
__device__ __forceinline__ void cpasync16(uint32_t dst, const void* src) {
    asm volatile("cp.async.cg.shared.global [%0], [%1], 16;" :: "r"(dst), "l"(src));
}
__device__ __forceinline__ void cp_commit() { asm volatile("cp.async.commit_group;" ::: "memory"); }
__device__ __forceinline__ void cp_wait1()  { asm volatile("cp.async.wait_group 1;" ::: "memory"); }
__device__ __forceinline__ void cp_wait0()  { asm volatile("cp.async.wait_group 0;" ::: "memory"); }
__device__ __forceinline__ uint32_t f2tf32(float f) {
    uint32_t u;
    asm("cvt.rna.tf32.f32 %0, %1;" : "=r"(u) : "f"(f));
    return u;
}
__device__ __forceinline__ float rnd_tf32(float f) {
    return __uint_as_float(f2tf32(f));
}
__device__ __forceinline__ void mma_tf32(float* c, const uint32_t* a, const uint32_t* b) {
    asm volatile(
        "mma.sync.aligned.m16n8k8.row.col.f32.tf32.tf32.f32 "
        "{%0,%1,%2,%3}, {%4,%5,%6,%7}, {%8,%9}, {%0,%1,%2,%3};"
        : "+f"(c[0]), "+f"(c[1]), "+f"(c[2]), "+f"(c[3])
        : "r"(a[0]), "r"(a[1]), "r"(a[2]), "r"(a[3]), "r"(b[0]), "r"(b[1]));
}

// ---------------------------------------------------------------------------
__global__ void round_pass(const float* __restrict__ in, float* __restrict__ outp, size_t n4)
{
    for (size_t i = blockIdx.x * blockDim.x + threadIdx.x; i < n4;
         i += (size_t)gridDim.x * blockDim.x) {
        float4 v = ((const float4*)in)[i];
        v.x = rnd_tf32(v.x); v.y = rnd_tf32(v.y);
        v.z = rnd_tf32(v.z); v.w = rnd_tf32(v.w);
        ((float4*)outp)[i] = v;
    }
}

// ---------------------------------------------------------------------------
// comb[h][wm][i][j] = bias[h,i,j] + mask[wm,i,j]  (i,j < 49), else -1e30
// ---------------------------------------------------------------------------
__global__ void comb_pre(const float* __restrict__ bt, const int* __restrict__ rel,
                         const float* __restrict__ mask, float* __restrict__ comb)
{
    const int total = NHEAD * 64 * 64 * 64;
    for (int t = blockIdx.x * blockDim.x + threadIdx.x; t < total;
         t += gridDim.x * blockDim.x) {
        int j = t & 63, i = (t >> 6) & 63, wm = (t >> 12) & 63, h = t >> 18;
        float val = -1e30f;
        if (i < NTOK && j < NTOK) {
            int e = i * NTOK + j;
            val = bt[rel[e] * NHEAD + h] + mask[(size_t)wm * 2401 + e];
        }
        comb[t] = val;
    }
}

// ---------------------------------------------------------------------------
// TF32 HMMA GEMM (proven): C = A * B^T + bias.  A,B pre-rounded tf32 floats.
// mode 0: scatter into q (scaled+rounded) / k / v head-major; mode 1: row-major.
// ---------------------------------------------------------------------------
#define PAD 36
#define BUFF 4608
#define SMEMB (4 * BUFF * 4)

__global__ __launch_bounds__(256, 2)
void gemm_tf32(const float* __restrict__ A, const float* __restrict__ Bm,
               const float* __restrict__ bias, float* __restrict__ outp,
               float* __restrict__ qo, float* __restrict__ ko, float* __restrict__ vo,
               int mode)
{
    extern __shared__ __align__(16) float sm[];
    const int tid = threadIdx.x;
    const int wid = tid >> 5, lane = tid & 31;
    const int wm = wid & 1, wn = wid >> 1;
    const int bn = blockIdx.x, bm = blockIdx.y;
    const uint32_t smb = s2u(sm);

    const int lrow = tid >> 3;
    const int lcol = (tid & 7) * 4;

    auto issue = [&](int ch) {
        const int st = ch & 1;
        const uint32_t da = smb + (size_t)(st * 2 * BUFF) * 4;
        const uint32_t db = da + BUFF * 4;
        const int kk = ch * 32;
        const float* ga = A  + (size_t)(bm * 128) * KDIM + kk;
        const float* gb = Bm + (size_t)(bn * 128) * KDIM + kk;
#pragma unroll
        for (int p = 0; p < 4; p++) {
            int r = lrow + p * 32;
            cpasync16(da + (r * PAD + lcol) * 4, ga + (size_t)r * KDIM + lcol);
            cpasync16(db + (r * PAD + lcol) * 4, gb + (size_t)r * KDIM + lcol);
        }
        cp_commit();
    };

    float cacc[4][4][4];
#pragma unroll
    for (int i = 0; i < 4; i++)
#pragma unroll
        for (int j = 0; j < 4; j++)
#pragma unroll
            for (int q = 0; q < 4; q++) cacc[i][j][q] = 0.f;

    issue(0);
    const int r4 = lane >> 2, c4 = lane & 3;

    for (int ch = 0; ch < 12; ch++) {
        if (ch + 1 < 12) issue(ch + 1);
        if (ch == 11) cp_wait0(); else cp_wait1();
        __syncthreads();

        const float* As = sm + (ch & 1) * 2 * BUFF;
        const float* Bs = As + BUFF;
#pragma unroll
        for (int k8 = 0; k8 < 4; k8++) {
            uint32_t af[4][4], bf[4][2];
#pragma unroll
            for (int mi = 0; mi < 4; mi++) {
                const uint32_t* ap = (const uint32_t*)(As + (wm * 64 + mi * 16 + r4) * PAD + k8 * 8 + c4);
                af[mi][0] = ap[0];
                af[mi][1] = ap[8 * PAD];
                af[mi][2] = ap[4];
                af[mi][3] = ap[8 * PAD + 4];
            }
#pragma unroll
            for (int ni = 0; ni < 4; ni++) {
                const uint32_t* bp = (const uint32_t*)(Bs + (wn * 32 + ni * 8 + r4) * PAD + k8 * 8 + c4);
                bf[ni][0] = bp[0];
                bf[ni][1] = bp[4];
            }
#pragma unroll
            for (int mi = 0; mi < 4; mi++)
#pragma unroll
                for (int ni = 0; ni < 4; ni++)
                    mma_tf32(cacc[mi][ni], af[mi], bf[ni]);
        }
        __syncthreads();
    }

    const float qscale = 0.17677669529663687f;   // 32^-0.5 folded into q
#pragma unroll
    for (int mi = 0; mi < 4; mi++) {
#pragma unroll
        for (int ni = 0; ni < 4; ni++) {
            const int m0 = bm * 128 + wm * 64 + mi * 16 + (lane >> 2);
            const int n0 = bn * 128 + wn * 32 + ni * 8 + 2 * (lane & 3);
            const float b0 = __ldg(bias + n0), b1 = __ldg(bias + n0 + 1);
            float2 v0 = { cacc[mi][ni][0] + b0, cacc[mi][ni][1] + b1 };
            float2 v1 = { cacc[mi][ni][2] + b0, cacc[mi][ni][3] + b1 };
            if (mode == 0) {
                const int arr = n0 / DIM, nin = n0 - arr * DIM;
                const int h = nin >> 5, d = nin & 31;
                if (arr == 0) { v0.x *= qscale; v0.y *= qscale; v1.x *= qscale; v1.y *= qscale; }
                v0.x = rnd_tf32(v0.x); v0.y = rnd_tf32(v0.y);
                v1.x = rnd_tf32(v1.x); v1.y = rnd_tf32(v1.y);
                float* basep = (arr == 0 ? qo : (arr == 1 ? ko : vo));
                int w0 = m0 / NTOK, i0 = m0 - w0 * NTOK;
                *(float2*)(basep + (((size_t)(w0 * NHEAD + h) * NTOK + i0) << 5) + d) = v0;
                int m1 = m0 + 8;
                int w1 = m1 / NTOK, i1 = m1 - w1 * NTOK;
                *(float2*)(basep + (((size_t)(w1 * NHEAD + h) * NTOK + i1) << 5) + d) = v1;
            } else {
                *(float2*)(outp + (size_t)m0 * DIM + n0) = v0;
                *(float2*)(outp + (size_t)(m0 + 8) * DIM + n0) = v1;
            }
        }
    }
}

// ---------------------------------------------------------------------------
// MMA attention, register softmax. Block per (h,w), 4 warps.
// Warp wid owns S rows [wid*16, +16) x all 64 cols -> row softmax needs only
// a 4-lane shfl reduction. P written once to smem, then P*V mma.
// ---------------------------------------------------------------------------
#define QP 36
#define SP 69
#define VP 68

__global__ __launch_bounds__(128)
void attn_mma(const float* __restrict__ qg, const float* __restrict__ kg,
              const float* __restrict__ vg, const float* __restrict__ comb,
              float* __restrict__ out)
{
    const int h = blockIdx.x, w = blockIdx.y, tid = threadIdx.x;
    const int wid = tid >> 5, lane = tid & 31;
    const int r4 = lane >> 2, c4 = lane & 3;

    __shared__ __align__(16) float qs[64][QP];
    __shared__ __align__(16) float ks[64][QP];
    __shared__ __align__(16) float vt[32][VP];
    __shared__ __align__(16) float ss[64][SP];

    // zero pads: q/k rows 49..63, vt cols 49..63
    for (int t = tid; t < 15 * QP; t += 128) {
        int r = t / QP, c = t - r * QP;
        qs[49 + r][c] = 0.f;
        ks[49 + r][c] = 0.f;
    }
    for (int t = tid; t < 32 * 15; t += 128) {
        int d = t / 15, j = t - d * 15;
        vt[d][49 + j] = 0.f;
    }

    const size_t base = ((size_t)(w * NHEAD + h) * NTOK) << 5;
    for (int t = tid; t < 49 * 32; t += 128) {
        int i = t >> 5, d = t & 31;
        qs[i][d] = qg[base + t];
        ks[i][d] = kg[base + t];
        vt[d][i] = vg[base + t];
    }
    __syncthreads();

    const int m0 = wid * 16;

    // ---- S = Q K^T (q pre-scaled), accumulators stay in registers ----
    float sacc[8][4];
#pragma unroll
    for (int ni = 0; ni < 8; ni++)
#pragma unroll
        for (int q = 0; q < 4; q++) sacc[ni][q] = 0.f;

#pragma unroll
    for (int k8 = 0; k8 < 4; k8++) {
        uint32_t af[4];
        const uint32_t* ap = (const uint32_t*)&qs[m0 + r4][k8 * 8 + c4];
        af[0] = ap[0];
        af[1] = ap[8 * QP];
        af[2] = ap[4];
        af[3] = ap[8 * QP + 4];
#pragma unroll
        for (int ni = 0; ni < 8; ni++) {
            uint32_t bf[2];
            const uint32_t* bp = (const uint32_t*)&ks[ni * 8 + r4][k8 * 8 + c4];
            bf[0] = bp[0];
            bf[1] = bp[4];
            mma_tf32(sacc[ni], af, bf);
        }
    }

    // ---- add comb (bias+mask, padded) directly into accumulators ----
    const float* cb = comb + (((size_t)h * 64 + (w & 63)) << 12);   // [64][64]
    const int i0 = m0 + r4, i1 = i0 + 8;
    float s0[16], s1[16];
#pragma unroll
    for (int ni = 0; ni < 8; ni++) {
        const int j0 = ni * 8 + 2 * c4;
        float2 c0 = *(const float2*)(cb + i0 * 64 + j0);
        float2 c1 = *(const float2*)(cb + i1 * 64 + j0);
        s0[2 * ni]     = sacc[ni][0] + c0.x;
        s0[2 * ni + 1] = sacc[ni][1] + c0.y;
        s1[2 * ni]     = sacc[ni][2] + c1.x;
        s1[2 * ni + 1] = sacc[ni][3] + c1.y;
    }

    // ---- register softmax over rows i0, i1 (4-lane groups share a row) ----
    float mx0 = -1e30f, mx1 = -1e30f;
#pragma unroll
    for (int t = 0; t < 16; t++) { mx0 = fmaxf(mx0, s0[t]); mx1 = fmaxf(mx1, s1[t]); }
#pragma unroll
    for (int o = 1; o <= 2; o <<= 1) {
        mx0 = fmaxf(mx0, __shfl_xor_sync(~0u, mx0, o));
        mx1 = fmaxf(mx1, __shfl_xor_sync(~0u, mx1, o));
    }
    float sum0 = 0.f, sum1 = 0.f;
#pragma unroll
    for (int t = 0; t < 16; t++) {
        s0[t] = __expf(s0[t] - mx0); sum0 += s0[t];
        s1[t] = __expf(s1[t] - mx1); sum1 += s1[t];
    }
#pragma unroll
    for (int o = 1; o <= 2; o <<= 1) {
        sum0 += __shfl_xor_sync(~0u, sum0, o);
        sum1 += __shfl_xor_sync(~0u, sum1, o);
    }
    const float inv0 = 1.0f / sum0, inv1 = 1.0f / sum1;

    // ---- write P (tf32-rounded) to smem; covers all 64x64 ----
#pragma unroll
    for (int ni = 0; ni < 8; ni++) {
        const int j0 = ni * 8 + 2 * c4;
        ss[i0][j0]     = rnd_tf32(s0[2 * ni] * inv0);
        ss[i0][j0 + 1] = rnd_tf32(s0[2 * ni + 1] * inv0);
        ss[i1][j0]     = rnd_tf32(s1[2 * ni] * inv1);
        ss[i1][j0 + 1] = rnd_tf32(s1[2 * ni + 1] * inv1);
    }
    __syncthreads();

    // ---- O = P V ----
    float oacc[4][4];
#pragma unroll
    for (int ni = 0; ni < 4; ni++)
#pragma unroll
        for (int q = 0; q < 4; q++) oacc[ni][q] = 0.f;

#pragma unroll
    for (int k8 = 0; k8 < 8; k8++) {
        uint32_t af[4];
        const uint32_t* ap = (const uint32_t*)&ss[m0 + r4][k8 * 8 + c4];
        af[0] = ap[0];
        af[1] = ap[8 * SP];
        af[2] = ap[4];
        af[3] = ap[8 * SP + 4];
#pragma unroll
        for (int ni = 0; ni < 4; ni++) {
            uint32_t bf[2];
            const uint32_t* bp = (const uint32_t*)&vt[ni * 8 + r4][k8 * 8 + c4];
            bf[0] = bp[0];
            bf[1] = bp[4];
            mma_tf32(oacc[ni], af, bf);
        }
    }

#pragma unroll
    for (int ni = 0; ni < 4; ni++) {
        const int d0 = ni * 8 + 2 * c4;
        if (i0 < 49) {
            float2 o0 = { rnd_tf32(oacc[ni][0]), rnd_tf32(oacc[ni][1]) };
            *(float2*)(out + ((size_t)w * 49 + i0) * DIM + h * 32 + d0) = o0;
        }
        if (i1 < 49) {
            float2 o1 = { rnd_tf32(oacc[ni][2]), rnd_tf32(oacc[ni][3]) };
            *(float2*)(out + ((size_t)w * 49 + i1) * DIM + h * 32 + d0) = o1;
        }
    }
}

// ---------------------------------------------------------------------------
extern "C" void kernel_launch(void* const* d_in, const int* in_sizes, int n_in,
                              void* d_out, int out_size)
{
    const float* x      = (const float*)d_in[0];
    const float* mask   = (const float*)d_in[1];
    const float* qkv_w  = (const float*)d_in[2];
    const float* qkv_b  = (const float*)d_in[3];
    const float* proj_w = (const float*)d_in[4];
    const float* proj_b = (const float*)d_in[5];
    const float* bt     = (const float*)d_in[6];
    const int*   rel    = (const int*)d_in[7];
    float* out = (float*)d_out;

    float *qp, *kp, *vp, *attp, *xr, *w1r, *w2r, *combp;
    cudaGetSymbolAddress((void**)&qp, g_q);
    cudaGetSymbolAddress((void**)&kp, g_k);
    cudaGetSymbolAddress((void**)&vp, g_v);
    cudaGetSymbolAddress((void**)&attp, g_att);
    cudaGetSymbolAddress((void**)&xr, g_xr);
    cudaGetSymbolAddress((void**)&w1r, g_w1r);
    cudaGetSymbolAddress((void**)&w2r, g_w2r);
    cudaGetSymbolAddress((void**)&combp, g_comb);

    cudaFuncSetAttribute(gemm_tf32, cudaFuncAttributeMaxDynamicSharedMemorySize, SMEMB);

    round_pass<<<1184, 256>>>(x, xr, (size_t)MROWS * DIM / 4);
    round_pass<<<112, 256>>>(qkv_w, w1r, (size_t)N1 * KDIM / 4);
    round_pass<<<48, 256>>>(proj_w, w2r, (size_t)DIM * KDIM / 4);
    comb_pre<<<1536, 256>>>(bt, rel, mask, combp);

    dim3 g1(N1 / 128, MROWS / 128);    // 9 x 1568
    gemm_tf32<<<g1, 256, SMEMB>>>(xr, w1r, qkv_b, nullptr, qp, kp, vp, 0);

    dim3 ga(NHEAD, BWIN);              // 12 x 4096
    attn_mma<<<ga, 128>>>(qp, kp, vp, combp, attp);

    dim3 g2(DIM / 128, MROWS / 128);   // 3 x 1568
    gemm_tf32<<<g2, 256, SMEMB>>>(attp, w2r, proj_b, out, nullptr, nullptr, nullptr, 1);
}

// round 8
// speedup vs baseline: 4.6289x; 1.0872x over previous
#include <cuda_runtime.h>
#include <cstdint>

#define DIM     384
#define NHEAD   12
#define NTOK    49
#define BWIN    4096
#define MROWS   (BWIN * NTOK)      // 200704
#define KDIM    384
#define N1      (3 * DIM)          // 1152

// ---------------- static device scratch ----------------
__device__ float g_q[(size_t)MROWS * DIM];
__device__ float g_k[(size_t)MROWS * DIM];
__device__ float g_v[(size_t)MROWS * DIM];
__device__ float g_att[(size_t)MROWS * DIM];
__device__ float g_xr[(size_t)MROWS * DIM];
__device__ float g_w1r[(size_t)N1 * KDIM];
__device__ float g_w2r[(size_t)DIM * KDIM];
__device__ float g_comb[(size_t)NHEAD * 64 * 64 * 64];   // bias+mask, padded

// ---------------- helpers ----------------
__device__ __forceinline__ uint32_t s2u(const void* p) {
    uint32_t a;
    asm("{ .reg .u64 t; cvta.to.shared.u64 t, %1; cvt.u32.u64 %0, t; }" : "=r"(a) : "l"(p));
    return a;
}
__device__ __forceinline__ void cpasync16(uint32_t dst, const void* src) {
    asm volatile("cp.async.cg.shared.global [%0], [%1], 16;" :: "r"(dst), "l"(src));
}
__device__ __forceinline__ void cp_commit() { asm volatile("cp.async.commit_group;" ::: "memory"); }
__device__ __forceinline__ void cp_wait1()  { asm volatile("cp.async.wait_group 1;" ::: "memory"); }
__device__ __forceinline__ void cp_wait0()  { asm volatile("cp.async.wait_group 0;" ::: "memory"); }
__device__ __forceinline__ uint32_t f2tf32(float f) {
    uint32_t u;
    asm("cvt.rna.tf32.f32 %0, %1;" : "=r"(u) : "f"(f));
    return u;
}
__device__ __forceinline__ float rnd_tf32(float f) {
    return __uint_as_float(f2tf32(f));
}
__device__ __forceinline__ void mma_tf32(float* c, const uint32_t* a, const uint32_t* b) {
    asm volatile(
        "mma.sync.aligned.m16n8k8.row.col.f32.tf32.tf32.f32 "
        "{%0,%1,%2,%3}, {%4,%5,%6,%7}, {%8,%9}, {%0,%1,%2,%3};"
        : "+f"(c[0]), "+f"(c[1]), "+f"(c[2]), "+f"(c[3])
        : "r"(a[0]), "r"(a[1]), "r"(a[2]), "r"(a[3]), "r"(b[0]), "r"(b[1]));
}

// ---------------------------------------------------------------------------
__global__ void round_pass(const float* __restrict__ in, float* __restrict__ outp, size_t n4)
{
    for (size_t i = blockIdx.x * blockDim.x + threadIdx.x; i < n4;
         i += (size_t)gridDim.x * blockDim.x) {
        float4 v = ((const float4*)in)[i];
        v.x = rnd_tf32(v.x); v.y = rnd_tf32(v.y);
        v.z = rnd_tf32(v.z); v.w = rnd_tf32(v.w);
        ((float4*)outp)[i] = v;
    }
}

// ---------------------------------------------------------------------------
// comb[h][wm][i][j] = bias[h,i,j] + mask[wm,i,j]  (i,j < 49), else -1e30
// ---------------------------------------------------------------------------
__global__ void comb_pre(const float* __restrict__ bt, const int* __restrict__ rel,
                         const float* __restrict__ mask, float* __restrict__ comb)
{
    const int total = NHEAD * 64 * 64 * 64;
    for (int t = blockIdx.x * blockDim.x + threadIdx.x; t < total;
         t += gridDim.x * blockDim.x) {
        int j = t & 63, i = (t >> 6) & 63, wm = (t >> 12) & 63, h = t >> 18;
        float val = -1e30f;
        if (i < NTOK && j < NTOK) {
            int e = i * NTOK + j;
            val = bt[rel[e] * NHEAD + h] + mask[(size_t)wm * 2401 + e];
        }
        comb[t] = val;
    }
}

// ---------------------------------------------------------------------------
// TF32 HMMA GEMM (proven): C = A * B^T + bias.  A,B pre-rounded tf32 floats.
// ---------------------------------------------------------------------------
#define PAD 36
#define BUFF 4608
#define SMEMB (4 * BUFF * 4)

__global__ __launch_bounds__(256, 2)
void gemm_tf32(const float* __restrict__ A, const float* __restrict__ Bm,
               const float* __restrict__ bias, float* __restrict__ outp,
               float* __restrict__ qo, float* __restrict__ ko, float* __restrict__ vo,
               int mode)
{
    extern __shared__ __align__(16) float sm[];
    const int tid = threadIdx.x;
    const int wid = tid >> 5, lane = tid & 31;
    const int wm = wid & 1, wn = wid >> 1;
    const int bn = blockIdx.x, bm = blockIdx.y;
    const uint32_t smb = s2u(sm);

    const int lrow = tid >> 3;
    const int lcol = (tid & 7) * 4;

    auto issue = [&](int ch) {
        const int st = ch & 1;
        const uint32_t da = smb + (size_t)(st * 2 * BUFF) * 4;
        const uint32_t db = da + BUFF * 4;
        const int kk = ch * 32;
        const float* ga = A  + (size_t)(bm * 128) * KDIM + kk;
        const float* gb = Bm + (size_t)(bn * 128) * KDIM + kk;
#pragma unroll
        for (int p = 0; p < 4; p++) {
            int r = lrow + p * 32;
            cpasync16(da + (r * PAD + lcol) * 4, ga + (size_t)r * KDIM + lcol);
            cpasync16(db + (r * PAD + lcol) * 4, gb + (size_t)r * KDIM + lcol);
        }
        cp_commit();
    };

    float cacc[4][4][4];
#pragma unroll
    for (int i = 0; i < 4; i++)
#pragma unroll
        for (int j = 0; j < 4; j++)
#pragma unroll
            for (int q = 0; q < 4; q++) cacc[i][j][q] = 0.f;

    issue(0);
    const int r4 = lane >> 2, c4 = lane & 3;

    for (int ch = 0; ch < 12; ch++) {
        if (ch + 1 < 12) issue(ch + 1);
        if (ch == 11) cp_wait0(); else cp_wait1();
        __syncthreads();

        const float* As = sm + (ch & 1) * 2 * BUFF;
        const float* Bs = As + BUFF;
#pragma unroll
        for (int k8 = 0; k8 < 4; k8++) {
            uint32_t af[4][4], bf[4][2];
#pragma unroll
            for (int mi = 0; mi < 4; mi++) {
                const uint32_t* ap = (const uint32_t*)(As + (wm * 64 + mi * 16 + r4) * PAD + k8 * 8 + c4);
                af[mi][0] = ap[0];
                af[mi][1] = ap[8 * PAD];
                af[mi][2] = ap[4];
                af[mi][3] = ap[8 * PAD + 4];
            }
#pragma unroll
            for (int ni = 0; ni < 4; ni++) {
                const uint32_t* bp = (const uint32_t*)(Bs + (wn * 32 + ni * 8 + r4) * PAD + k8 * 8 + c4);
                bf[ni][0] = bp[0];
                bf[ni][1] = bp[4];
            }
#pragma unroll
            for (int mi = 0; mi < 4; mi++)
#pragma unroll
                for (int ni = 0; ni < 4; ni++)
                    mma_tf32(cacc[mi][ni], af[mi], bf[ni]);
        }
        __syncthreads();
    }

    const float qscale = 0.17677669529663687f;   // 32^-0.5 folded into q
#pragma unroll
    for (int mi = 0; mi < 4; mi++) {
#pragma unroll
        for (int ni = 0; ni < 4; ni++) {
            const int m0 = bm * 128 + wm * 64 + mi * 16 + (lane >> 2);
            const int n0 = bn * 128 + wn * 32 + ni * 8 + 2 * (lane & 3);
            const float b0 = __ldg(bias + n0), b1 = __ldg(bias + n0 + 1);
            float2 v0 = { cacc[mi][ni][0] + b0, cacc[mi][ni][1] + b1 };
            float2 v1 = { cacc[mi][ni][2] + b0, cacc[mi][ni][3] + b1 };
            if (mode == 0) {
                const int arr = n0 / DIM, nin = n0 - arr * DIM;
                const int h = nin >> 5, d = nin & 31;
                if (arr == 0) { v0.x *= qscale; v0.y *= qscale; v1.x *= qscale; v1.y *= qscale; }
                v0.x = rnd_tf32(v0.x); v0.y = rnd_tf32(v0.y);
                v1.x = rnd_tf32(v1.x); v1.y = rnd_tf32(v1.y);
                float* basep = (arr == 0 ? qo : (arr == 1 ? ko : vo));
                int w0 = m0 / NTOK, i0 = m0 - w0 * NTOK;
                *(float2*)(basep + (((size_t)(w0 * NHEAD + h) * NTOK + i0) << 5) + d) = v0;
                int m1 = m0 + 8;
                int w1 = m1 / NTOK, i1 = m1 - w1 * NTOK;
                *(float2*)(basep + (((size_t)(w1 * NHEAD + h) * NTOK + i1) << 5) + d) = v1;
            } else {
                *(float2*)(outp + (size_t)m0 * DIM + n0) = v0;
                *(float2*)(outp + (size_t)(m0 + 8) * DIM + n0) = v1;
            }
        }
    }
}

// ---------------------------------------------------------------------------
// MMA attention, register softmax, smem-aliased (qs/ks reused as ss).
// Block per (h,w), 4 warps, targeted 8 blocks/SM.
// ---------------------------------------------------------------------------
#define QP 36
#define SP 69
#define VP 68

__global__ __launch_bounds__(128, 8)
void attn_mma(const float* __restrict__ qg, const float* __restrict__ kg,
              const float* __restrict__ vg, const float* __restrict__ comb,
              float* __restrict__ out)
{
    const int h = blockIdx.x, w = blockIdx.y, tid = threadIdx.x;
    const int wid = tid >> 5, lane = tid & 31;
    const int r4 = lane >> 2, c4 = lane & 3;

    __shared__ __align__(16) union SU {
        struct { float qs[64][QP]; float ks[64][QP]; } a;   // 18432 B
        float ss[64][SP];                                   // 17664 B
    } u;
    __shared__ __align__(16) float vt[32][VP];              // 8704 B

    float (*qs)[QP] = u.a.qs;
    float (*ks)[QP] = u.a.ks;

    // zero pads: q/k rows 49..63, vt cols 49..63
    for (int t = tid; t < 15 * QP; t += 128) {
        int r = t / QP, c = t - r * QP;
        qs[49 + r][c] = 0.f;
        ks[49 + r][c] = 0.f;
    }
    for (int t = tid; t < 32 * 15; t += 128) {
        int d = t / 15, j = t - d * 15;
        vt[d][49 + j] = 0.f;
    }

    const size_t base = ((size_t)(w * NHEAD + h) * NTOK) << 5;
    for (int t = tid; t < 49 * 32; t += 128) {
        int i = t >> 5, d = t & 31;
        qs[i][d] = qg[base + t];
        ks[i][d] = kg[base + t];
        vt[d][i] = vg[base + t];
    }
    __syncthreads();

    const int m0 = wid * 16;

    // ---- S = Q K^T (q pre-scaled), accumulators in registers ----
    float sacc[8][4];
#pragma unroll
    for (int ni = 0; ni < 8; ni++)
#pragma unroll
        for (int q = 0; q < 4; q++) sacc[ni][q] = 0.f;

#pragma unroll
    for (int k8 = 0; k8 < 4; k8++) {
        uint32_t af[4];
        const uint32_t* ap = (const uint32_t*)&qs[m0 + r4][k8 * 8 + c4];
        af[0] = ap[0];
        af[1] = ap[8 * QP];
        af[2] = ap[4];
        af[3] = ap[8 * QP + 4];
#pragma unroll
        for (int ni = 0; ni < 8; ni++) {
            uint32_t bf[2];
            const uint32_t* bp = (const uint32_t*)&ks[ni * 8 + r4][k8 * 8 + c4];
            bf[0] = bp[0];
            bf[1] = bp[4];
            mma_tf32(sacc[ni], af, bf);
        }
    }

    // ---- add comb (bias+mask) in place ----
    const float* cb = comb + (((size_t)h * 64 + (w & 63)) << 12);   // [64][64]
    const int i0 = m0 + r4, i1 = i0 + 8;
#pragma unroll
    for (int ni = 0; ni < 8; ni++) {
        const int j0 = ni * 8 + 2 * c4;
        float2 c0 = *(const float2*)(cb + i0 * 64 + j0);
        float2 c1 = *(const float2*)(cb + i1 * 64 + j0);
        sacc[ni][0] += c0.x;
        sacc[ni][1] += c0.y;
        sacc[ni][2] += c1.x;
        sacc[ni][3] += c1.y;
    }

    // ---- register softmax (rows i0 via [0,1], i1 via [2,3]; 4-lane groups) ----
    float mx0 = -1e30f, mx1 = -1e30f;
#pragma unroll
    for (int ni = 0; ni < 8; ni++) {
        mx0 = fmaxf(mx0, fmaxf(sacc[ni][0], sacc[ni][1]));
        mx1 = fmaxf(mx1, fmaxf(sacc[ni][2], sacc[ni][3]));
    }
#pragma unroll
    for (int o = 1; o <= 2; o <<= 1) {
        mx0 = fmaxf(mx0, __shfl_xor_sync(~0u, mx0, o));
        mx1 = fmaxf(mx1, __shfl_xor_sync(~0u, mx1, o));
    }
    float sum0 = 0.f, sum1 = 0.f;
#pragma unroll
    for (int ni = 0; ni < 8; ni++) {
        sacc[ni][0] = __expf(sacc[ni][0] - mx0); sum0 += sacc[ni][0];
        sacc[ni][1] = __expf(sacc[ni][1] - mx0); sum0 += sacc[ni][1];
        sacc[ni][2] = __expf(sacc[ni][2] - mx1); sum1 += sacc[ni][2];
        sacc[ni][3] = __expf(sacc[ni][3] - mx1); sum1 += sacc[ni][3];
    }
#pragma unroll
    for (int o = 1; o <= 2; o <<= 1) {
        sum0 += __shfl_xor_sync(~0u, sum0, o);
        sum1 += __shfl_xor_sync(~0u, sum1, o);
    }
    const float inv0 = 1.0f / sum0, inv1 = 1.0f / sum1;

    // all qs/ks reads done in every warp before ss overwrite
    __syncthreads();

    // ---- write P (tf32-rounded) into aliased ss ----
#pragma unroll
    for (int ni = 0; ni < 8; ni++) {
        const int j0 = ni * 8 + 2 * c4;
        u.ss[i0][j0]     = rnd_tf32(sacc[ni][0] * inv0);
        u.ss[i0][j0 + 1] = rnd_tf32(sacc[ni][1] * inv0);
        u.ss[i1][j0]     = rnd_tf32(sacc[ni][2] * inv1);
        u.ss[i1][j0 + 1] = rnd_tf32(sacc[ni][3] * inv1);
    }
    __syncthreads();

    // ---- O = P V ----
    float oacc[4][4];
#pragma unroll
    for (int ni = 0; ni < 4; ni++)
#pragma unroll
        for (int q = 0; q < 4; q++) oacc[ni][q] = 0.f;

#pragma unroll
    for (int k8 = 0; k8 < 8; k8++) {
        uint32_t af[4];
        const uint32_t* ap = (const uint32_t*)&u.ss[m0 + r4][k8 * 8 + c4];
        af[0] = ap[0];
        af[1] = ap[8 * SP];
        af[2] = ap[4];
        af[3] = ap[8 * SP + 4];
#pragma unroll
        for (int ni = 0; ni < 4; ni++) {
            uint32_t bf[2];
            const uint32_t* bp = (const uint32_t*)&vt[ni * 8 + r4][k8 * 8 + c4];
            bf[0] = bp[0];
            bf[1] = bp[4];
            mma_tf32(oacc[ni], af, bf);
        }
    }

#pragma unroll
    for (int ni = 0; ni < 4; ni++) {
        const int d0 = ni * 8 + 2 * c4;
        if (i0 < 49) {
            float2 o0 = { rnd_tf32(oacc[ni][0]), rnd_tf32(oacc[ni][1]) };
            *(float2*)(out + ((size_t)w * 49 + i0) * DIM + h * 32 + d0) = o0;
        }
        if (i1 < 49) {
            float2 o1 = { rnd_tf32(oacc[ni][2]), rnd_tf32(oacc[ni][3]) };
            *(float2*)(out + ((size_t)w * 49 + i1) * DIM + h * 32 + d0) = o1;
        }
    }
}

// ---------------------------------------------------------------------------
extern "C" void kernel_launch(void* const* d_in, const int* in_sizes, int n_in,
                              void* d_out, int out_size)
{
    const float* x      = (const float*)d_in[0];
    const float* mask   = (const float*)d_in[1];
    const float* qkv_w  = (const float*)d_in[2];
    const float* qkv_b  = (const float*)d_in[3];
    const float* proj_w = (const float*)d_in[4];
    const float* proj_b = (const float*)d_in[5];
    const float* bt     = (const float*)d_in[6];
    const int*   rel    = (const int*)d_in[7];
    float* out = (float*)d_out;

    float *qp, *kp, *vp, *attp, *xr, *w1r, *w2r, *combp;
    cudaGetSymbolAddress((void**)&qp, g_q);
    cudaGetSymbolAddress((void**)&kp, g_k);
    cudaGetSymbolAddress((void**)&vp, g_v);
    cudaGetSymbolAddress((void**)&attp, g_att);
    cudaGetSymbolAddress((void**)&xr, g_xr);
    cudaGetSymbolAddress((void**)&w1r, g_w1r);
    cudaGetSymbolAddress((void**)&w2r, g_w2r);
    cudaGetSymbolAddress((void**)&combp, g_comb);

    cudaFuncSetAttribute(gemm_tf32, cudaFuncAttributeMaxDynamicSharedMemorySize, SMEMB);

    round_pass<<<1184, 256>>>(x, xr, (size_t)MROWS * DIM / 4);
    round_pass<<<112, 256>>>(qkv_w, w1r, (size_t)N1 * KDIM / 4);
    round_pass<<<48, 256>>>(proj_w, w2r, (size_t)DIM * KDIM / 4);
    comb_pre<<<1536, 256>>>(bt, rel, mask, combp);

    dim3 g1(N1 / 128, MROWS / 128);    // 9 x 1568
    gemm_tf32<<<g1, 256, SMEMB>>>(xr, w1r, qkv_b, nullptr, qp, kp, vp, 0);

    dim3 ga(NHEAD, BWIN);              // 12 x 4096
    attn_mma<<<ga, 128>>>(qp, kp, vp, combp, attp);

    dim3 g2(DIM / 128, MROWS / 128);   // 3 x 1568
    gemm_tf32<<<g2, 256, SMEMB>>>(attp, w2r, proj_b, out, nullptr, nullptr, nullptr, 1);
}

// round 9
// speedup vs baseline: 5.6090x; 1.2118x over previous
#include <cuda_runtime.h>
#include <cuda_fp16.h>
#include <cstdint>

#define DIM     384
#define NHEAD   12
#define NTOK    49
#define BWIN    4096
#define MROWS   (BWIN * NTOK)      // 200704
#define KDIM    384
#define N1      (3 * DIM)          // 1152

// ---------------- static device scratch ----------------
__device__ float  g_q[(size_t)MROWS * DIM];
__device__ float  g_k[(size_t)MROWS * DIM];
__device__ float  g_v[(size_t)MROWS * DIM];
__device__ __half g_xh[(size_t)MROWS * DIM];
__device__ __half g_atth[(size_t)MROWS * DIM];
__device__ __half g_w1h[(size_t)N1 * KDIM];
__device__ __half g_w2h[(size_t)DIM * KDIM];
__device__ float  g_comb[(size_t)NHEAD * 64 * 64 * 64];   // bias+mask, padded

// ---------------- helpers ----------------
__device__ __forceinline__ uint32_t s2u(const void* p) {
    uint32_t a;
    asm("{ .reg .u64 t; cvta.to.shared.u64 t, %1; cvt.u32.u64 %0, t; }" : "=r"(a) : "l"(p));
    return a;
}
__device__ __forceinline__ void cpasync16(uint32_t dst, const void* src) {
    asm volatile("cp.async.cg.shared.global [%0], [%1], 16;" :: "r"(dst), "l"(src));
}
__device__ __forceinline__ void cp_commit() { asm volatile("cp.async.commit_group;" ::: "memory"); }
__device__ __forceinline__ void cp_wait1()  { asm volatile("cp.async.wait_group 1;" ::: "memory"); }
__device__ __forceinline__ void cp_wait0()  { asm volatile("cp.async.wait_group 0;" ::: "memory"); }
__device__ __forceinline__ uint32_t f2tf32(float f) {
    uint32_t u;
    asm("cvt.rna.tf32.f32 %0, %1;" : "=r"(u) : "f"(f));
    return u;
}
__device__ __forceinline__ float rnd_tf32(float f) {
    return __uint_as_float(f2tf32(f));
}
__device__ __forceinline__ void mma_tf32(float* c, const uint32_t* a, const uint32_t* b) {
    asm volatile(
        "mma.sync.aligned.m16n8k8.row.col.f32.tf32.tf32.f32 "
        "{%0,%1,%2,%3}, {%4,%5,%6,%7}, {%8,%9}, {%0,%1,%2,%3};"
        : "+f"(c[0]), "+f"(c[1]), "+f"(c[2]), "+f"(c[3])
        : "r"(a[0]), "r"(a[1]), "r"(a[2]), "r"(a[3]), "r"(b[0]), "r"(b[1]));
}
__device__ __forceinline__ void mma_f16(float* c, const uint32_t* a, const uint32_t* b) {
    asm volatile(
        "mma.sync.aligned.m16n8k16.row.col.f32.f16.f16.f32 "
        "{%0,%1,%2,%3}, {%4,%5,%6,%7}, {%8,%9}, {%0,%1,%2,%3};"
        : "+f"(c[0]), "+f"(c[1]), "+f"(c[2]), "+f"(c[3])
        : "r"(a[0]), "r"(a[1]), "r"(a[2]), "r"(a[3]), "r"(b[0]), "r"(b[1]));
}

// ---------------------------------------------------------------------------
// fp32 -> fp16 conversion pass (vectorized, grid-stride)
// ---------------------------------------------------------------------------
__global__ void half_pass(const float* __restrict__ in, __half* __restrict__ outp, size_t n4)
{
    for (size_t i = blockIdx.x * blockDim.x + threadIdx.x; i < n4;
         i += (size_t)gridDim.x * blockDim.x) {
        float4 v = ((const float4*)in)[i];
        __half2 h0 = __floats2half2_rn(v.x, v.y);
        __half2 h1 = __floats2half2_rn(v.z, v.w);
        uint2 pk = { *(uint32_t*)&h0, *(uint32_t*)&h1 };
        ((uint2*)outp)[i] = pk;
    }
}

// ---------------------------------------------------------------------------
// comb[h][wm][i][j] = bias[h,i,j] + mask[wm,i,j]  (i,j < 49), else -1e30
// ---------------------------------------------------------------------------
__global__ void comb_pre(const float* __restrict__ bt, const int* __restrict__ rel,
                         const float* __restrict__ mask, float* __restrict__ comb)
{
    const int total = NHEAD * 64 * 64 * 64;
    for (int t = blockIdx.x * blockDim.x + threadIdx.x; t < total;
         t += gridDim.x * blockDim.x) {
        int j = t & 63, i = (t >> 6) & 63, wm = (t >> 12) & 63, h = t >> 18;
        float val = -1e30f;
        if (i < NTOK && j < NTOK) {
            int e = i * NTOK + j;
            val = bt[rel[e] * NHEAD + h] + mask[(size_t)wm * 2401 + e];
        }
        comb[t] = val;
    }
}

// ---------------------------------------------------------------------------
// FP16 HMMA GEMM: C = A * B^T + bias.  A,B fp16 [rows][384] halves.
// Block 128x128, BK=64, 8 warps (2m x 4n), warp tile 64x32, m16n8k16.
// mode 0: scatter into q (scaled, tf32-rounded) / k / v head-major fp32
// mode 1: row-major fp32 out + bias
// ---------------------------------------------------------------------------
#define PADH 72
#define HBUFF (128 * PADH)            // halves per operand buffer
#define SMEMH (4 * HBUFF * 2)         // bytes: 2 stages x (A+B) = 73728

__global__ __launch_bounds__(256, 2)
void gemm_f16(const __half* __restrict__ A, const __half* __restrict__ Bm,
              const float* __restrict__ bias, float* __restrict__ outp,
              float* __restrict__ qo, float* __restrict__ ko, float* __restrict__ vo,
              int mode)
{
    extern __shared__ __align__(16) __half smh[];
    const int tid = threadIdx.x;
    const int wid = tid >> 5, lane = tid & 31;
    const int wm = wid & 1, wn = wid >> 1;
    const int bn = blockIdx.x, bm = blockIdx.y;
    const uint32_t smb = s2u(smh);

    const int lrow = tid >> 1;                 // 0..127
    const int lcol0 = (tid & 1) * 32;          // half offset

    auto issue = [&](int ch) {
        const int st = ch & 1;
        const uint32_t da = smb + (uint32_t)(st * 2 * HBUFF) * 2;
        const uint32_t db = da + HBUFF * 2;
        const int kk = ch * 64;
        const __half* ga = A  + (size_t)(bm * 128) * KDIM + kk;
        const __half* gb = Bm + (size_t)(bn * 128) * KDIM + kk;
#pragma unroll
        for (int p = 0; p < 4; p++) {
            int c = lcol0 + p * 8;
            cpasync16(da + (lrow * PADH + c) * 2, ga + (size_t)lrow * KDIM + c);
            cpasync16(db + (lrow * PADH + c) * 2, gb + (size_t)lrow * KDIM + c);
        }
        cp_commit();
    };

    float cacc[4][4][4];
#pragma unroll
    for (int i = 0; i < 4; i++)
#pragma unroll
        for (int j = 0; j < 4; j++)
#pragma unroll
            for (int q = 0; q < 4; q++) cacc[i][j][q] = 0.f;

    issue(0);
    const int r4 = lane >> 2, c4 = lane & 3;

    for (int ch = 0; ch < 6; ch++) {
        if (ch + 1 < 6) issue(ch + 1);
        if (ch == 5) cp_wait0(); else cp_wait1();
        __syncthreads();

        const __half* As = smh + (ch & 1) * 2 * HBUFF;
        const __half* Bs = As + HBUFF;
#pragma unroll
        for (int k16 = 0; k16 < 4; k16++) {
            uint32_t af[4][4], bf[4][2];
#pragma unroll
            for (int mi = 0; mi < 4; mi++) {
                const __half* ap = As + (wm * 64 + mi * 16 + r4) * PADH + k16 * 16 + 2 * c4;
                af[mi][0] = *(const uint32_t*)ap;
                af[mi][1] = *(const uint32_t*)(ap + 8 * PADH);
                af[mi][2] = *(const uint32_t*)(ap + 8);
                af[mi][3] = *(const uint32_t*)(ap + 8 * PADH + 8);
            }
#pragma unroll
            for (int ni = 0; ni < 4; ni++) {
                const __half* bp = Bs + (wn * 32 + ni * 8 + r4) * PADH + k16 * 16 + 2 * c4;
                bf[ni][0] = *(const uint32_t*)bp;
                bf[ni][1] = *(const uint32_t*)(bp + 8);
            }
#pragma unroll
            for (int mi = 0; mi < 4; mi++)
#pragma unroll
                for (int ni = 0; ni < 4; ni++)
                    mma_f16(cacc[mi][ni], af[mi], bf[ni]);
        }
        __syncthreads();
    }

    const float qscale = 0.17677669529663687f;   // 32^-0.5 folded into q
#pragma unroll
    for (int mi = 0; mi < 4; mi++) {
#pragma unroll
        for (int ni = 0; ni < 4; ni++) {
            const int m0 = bm * 128 + wm * 64 + mi * 16 + (lane >> 2);
            const int n0 = bn * 128 + wn * 32 + ni * 8 + 2 * (lane & 3);
            const float b0 = __ldg(bias + n0), b1 = __ldg(bias + n0 + 1);
            float2 v0 = { cacc[mi][ni][0] + b0, cacc[mi][ni][1] + b1 };
            float2 v1 = { cacc[mi][ni][2] + b0, cacc[mi][ni][3] + b1 };
            if (mode == 0) {
                const int arr = n0 / DIM, nin = n0 - arr * DIM;
                const int h = nin >> 5, d = nin & 31;
                if (arr == 0) { v0.x *= qscale; v0.y *= qscale; v1.x *= qscale; v1.y *= qscale; }
                v0.x = rnd_tf32(v0.x); v0.y = rnd_tf32(v0.y);
                v1.x = rnd_tf32(v1.x); v1.y = rnd_tf32(v1.y);
                float* basep = (arr == 0 ? qo : (arr == 1 ? ko : vo));
                int w0 = m0 / NTOK, i0 = m0 - w0 * NTOK;
                *(float2*)(basep + (((size_t)(w0 * NHEAD + h) * NTOK + i0) << 5) + d) = v0;
                int m1 = m0 + 8;
                int w1 = m1 / NTOK, i1 = m1 - w1 * NTOK;
                *(float2*)(basep + (((size_t)(w1 * NHEAD + h) * NTOK + i1) << 5) + d) = v1;
            } else {
                *(float2*)(outp + (size_t)m0 * DIM + n0) = v0;
                *(float2*)(outp + (size_t)(m0 + 8) * DIM + n0) = v1;
            }
        }
    }
}

// ---------------------------------------------------------------------------
// MMA attention (tf32, proven): register softmax, smem aliasing.
// Output written as fp16 (gemm2's A operand).
// ---------------------------------------------------------------------------
#define QP 36
#define SP 69
#define VP 68

__global__ __launch_bounds__(128, 8)
void attn_mma(const float* __restrict__ qg, const float* __restrict__ kg,
              const float* __restrict__ vg, const float* __restrict__ comb,
              __half* __restrict__ out)
{
    const int h = blockIdx.x, w = blockIdx.y, tid = threadIdx.x;
    const int wid = tid >> 5, lane = tid & 31;
    const int r4 = lane >> 2, c4 = lane & 3;

    __shared__ __align__(16) union SU {
        struct { float qs[64][QP]; float ks[64][QP]; } a;
        float ss[64][SP];
    } u;
    __shared__ __align__(16) float vt[32][VP];

    float (*qs)[QP] = u.a.qs;
    float (*ks)[QP] = u.a.ks;

    for (int t = tid; t < 15 * QP; t += 128) {
        int r = t / QP, c = t - r * QP;
        qs[49 + r][c] = 0.f;
        ks[49 + r][c] = 0.f;
    }
    for (int t = tid; t < 32 * 15; t += 128) {
        int d = t / 15, j = t - d * 15;
        vt[d][49 + j] = 0.f;
    }

    const size_t base = ((size_t)(w * NHEAD + h) * NTOK) << 5;
    for (int t = tid; t < 49 * 32; t += 128) {
        int i = t >> 5, d = t & 31;
        qs[i][d] = qg[base + t];
        ks[i][d] = kg[base + t];
        vt[d][i] = vg[base + t];
    }
    __syncthreads();

    const int m0 = wid * 16;

    float sacc[8][4];
#pragma unroll
    for (int ni = 0; ni < 8; ni++)
#pragma unroll
        for (int q = 0; q < 4; q++) sacc[ni][q] = 0.f;

#pragma unroll
    for (int k8 = 0; k8 < 4; k8++) {
        uint32_t af[4];
        const uint32_t* ap = (const uint32_t*)&qs[m0 + r4][k8 * 8 + c4];
        af[0] = ap[0];
        af[1] = ap[8 * QP];
        af[2] = ap[4];
        af[3] = ap[8 * QP + 4];
#pragma unroll
        for (int ni = 0; ni < 8; ni++) {
            uint32_t bf[2];
            const uint32_t* bp = (const uint32_t*)&ks[ni * 8 + r4][k8 * 8 + c4];
            bf[0] = bp[0];
            bf[1] = bp[4];
            mma_tf32(sacc[ni], af, bf);
        }
    }

    const float* cb = comb + (((size_t)h * 64 + (w & 63)) << 12);
    const int i0 = m0 + r4, i1 = i0 + 8;
#pragma unroll
    for (int ni = 0; ni < 8; ni++) {
        const int j0 = ni * 8 + 2 * c4;
        float2 c0 = *(const float2*)(cb + i0 * 64 + j0);
        float2 c1 = *(const float2*)(cb + i1 * 64 + j0);
        sacc[ni][0] += c0.x;
        sacc[ni][1] += c0.y;
        sacc[ni][2] += c1.x;
        sacc[ni][3] += c1.y;
    }

    float mx0 = -1e30f, mx1 = -1e30f;
#pragma unroll
    for (int ni = 0; ni < 8; ni++) {
        mx0 = fmaxf(mx0, fmaxf(sacc[ni][0], sacc[ni][1]));
        mx1 = fmaxf(mx1, fmaxf(sacc[ni][2], sacc[ni][3]));
    }
#pragma unroll
    for (int o = 1; o <= 2; o <<= 1) {
        mx0 = fmaxf(mx0, __shfl_xor_sync(~0u, mx0, o));
        mx1 = fmaxf(mx1, __shfl_xor_sync(~0u, mx1, o));
    }
    float sum0 = 0.f, sum1 = 0.f;
#pragma unroll
    for (int ni = 0; ni < 8; ni++) {
        sacc[ni][0] = __expf(sacc[ni][0] - mx0); sum0 += sacc[ni][0];
        sacc[ni][1] = __expf(sacc[ni][1] - mx0); sum0 += sacc[ni][1];
        sacc[ni][2] = __expf(sacc[ni][2] - mx1); sum1 += sacc[ni][2];
        sacc[ni][3] = __expf(sacc[ni][3] - mx1); sum1 += sacc[ni][3];
    }
#pragma unroll
    for (int o = 1; o <= 2; o <<= 1) {
        sum0 += __shfl_xor_sync(~0u, sum0, o);
        sum1 += __shfl_xor_sync(~0u, sum1, o);
    }
    const float inv0 = 1.0f / sum0, inv1 = 1.0f / sum1;

    __syncthreads();

#pragma unroll
    for (int ni = 0; ni < 8; ni++) {
        const int j0 = ni * 8 + 2 * c4;
        u.ss[i0][j0]     = rnd_tf32(sacc[ni][0] * inv0);
        u.ss[i0][j0 + 1] = rnd_tf32(sacc[ni][1] * inv0);
        u.ss[i1][j0]     = rnd_tf32(sacc[ni][2] * inv1);
        u.ss[i1][j0 + 1] = rnd_tf32(sacc[ni][3] * inv1);
    }
    __syncthreads();

    float oacc[4][4];
#pragma unroll
    for (int ni = 0; ni < 4; ni++)
#pragma unroll
        for (int q = 0; q < 4; q++) oacc[ni][q] = 0.f;

#pragma unroll
    for (int k8 = 0; k8 < 8; k8++) {
        uint32_t af[4];
        const uint32_t* ap = (const uint32_t*)&u.ss[m0 + r4][k8 * 8 + c4];
        af[0] = ap[0];
        af[1] = ap[8 * SP];
        af[2] = ap[4];
        af[3] = ap[8 * SP + 4];
#pragma unroll
        for (int ni = 0; ni < 4; ni++) {
            uint32_t bf[2];
            const uint32_t* bp = (const uint32_t*)&vt[ni * 8 + r4][k8 * 8 + c4];
            bf[0] = bp[0];
            bf[1] = bp[4];
            mma_tf32(oacc[ni], af, bf);
        }
    }

#pragma unroll
    for (int ni = 0; ni < 4; ni++) {
        const int d0 = ni * 8 + 2 * c4;
        if (i0 < 49) {
            __half2 o0 = __floats2half2_rn(oacc[ni][0], oacc[ni][1]);
            *(__half2*)(out + ((size_t)w * 49 + i0) * DIM + h * 32 + d0) = o0;
        }
        if (i1 < 49) {
            __half2 o1 = __floats2half2_rn(oacc[ni][2], oacc[ni][3]);
            *(__half2*)(out + ((size_t)w * 49 + i1) * DIM + h * 32 + d0) = o1;
        }
    }
}

// ---------------------------------------------------------------------------
extern "C" void kernel_launch(void* const* d_in, const int* in_sizes, int n_in,
                              void* d_out, int out_size)
{
    const float* x      = (const float*)d_in[0];
    const float* mask   = (const float*)d_in[1];
    const float* qkv_w  = (const float*)d_in[2];
    const float* qkv_b  = (const float*)d_in[3];
    const float* proj_w = (const float*)d_in[4];
    const float* proj_b = (const float*)d_in[5];
    const float* bt     = (const float*)d_in[6];
    const int*   rel    = (const int*)d_in[7];
    float* out = (float*)d_out;

    float *qp, *kp, *vp, *combp;
    __half *xh, *atth, *w1h, *w2h;
    cudaGetSymbolAddress((void**)&qp, g_q);
    cudaGetSymbolAddress((void**)&kp, g_k);
    cudaGetSymbolAddress((void**)&vp, g_v);
    cudaGetSymbolAddress((void**)&combp, g_comb);
    cudaGetSymbolAddress((void**)&xh, g_xh);
    cudaGetSymbolAddress((void**)&atth, g_atth);
    cudaGetSymbolAddress((void**)&w1h, g_w1h);
    cudaGetSymbolAddress((void**)&w2h, g_w2h);

    cudaFuncSetAttribute(gemm_f16, cudaFuncAttributeMaxDynamicSharedMemorySize, SMEMH);

    half_pass<<<1184, 256>>>(x, xh, (size_t)MROWS * DIM / 4);
    half_pass<<<112, 256>>>(qkv_w, w1h, (size_t)N1 * KDIM / 4);
    half_pass<<<48, 256>>>(proj_w, w2h, (size_t)DIM * KDIM / 4);
    comb_pre<<<1536, 256>>>(bt, rel, mask, combp);

    dim3 g1(N1 / 128, MROWS / 128);    // 9 x 1568
    gemm_f16<<<g1, 256, SMEMH>>>(xh, w1h, qkv_b, nullptr, qp, kp, vp, 0);

    dim3 ga(NHEAD, BWIN);              // 12 x 4096
    attn_mma<<<ga, 128>>>(qp, kp, vp, combp, atth);

    dim3 g2(DIM / 128, MROWS / 128);   // 3 x 1568
    gemm_f16<<<g2, 256, SMEMH>>>(atth, w2h, proj_b, out, nullptr, nullptr, nullptr, 1);
}